// round 11
// baseline (speedup 1.0000x reference)
#include <cuda_runtime.h>
#include <cuda_bf16.h>
#include <math.h>
#include <stdint.h>

#define Bv 4
#define Tv 4096
#define Cv 512
#define Rv (Bv*Tv)            // 16384 rows
#define Fv (4*Cv)             // 2048
#define GUARDE (2048*Cv)      // guard rows (zero-init) for shifted scan operand
#define Sm ((long)Cv*Cv)

typedef __nv_bfloat16 bf16;

// ---------------- static device scratch (zero-initialized) ----------------
__device__ bf16 g_qH[GUARDE + Rv*Cv];
__device__ bf16 g_qL[GUARDE + Rv*Cv];
__device__ bf16 g_vH[Rv*Cv], g_vL[Rv*Cv];
__device__ float g_z[Rv*Cv];
__device__ bf16 g_hH[Rv*Cv], g_hL[Rv*Cv];
__device__ bf16 g_fcH[Rv*Fv], g_fcL[Rv*Fv];
// weight splits
__device__ bf16 g_WqH[Cv*Cv], g_WqL[Cv*Cv];
__device__ bf16 g_WvH[Cv*Cv], g_WvL[Cv*Cv];
__device__ bf16 g_WoH[Cv*Cv], g_WoL[Cv*Cv];
__device__ bf16 g_WfcH[Fv*Cv], g_WfcL[Fv*Cv];
__device__ bf16 g_WprH[Cv*Fv], g_WprL[Cv*Fv];
// polar scratch (x2 matrices, batched)
__device__ bf16 g_XaH[2*Cv*Cv], g_XaL[2*Cv*Cv];
__device__ bf16 g_XbH[2*Cv*Cv], g_XbL[2*Cv*Cv];
__device__ bf16 g_XtH[2*Cv*Cv], g_XtL[2*Cv*Cv];
__device__ bf16 g_YH [2*Cv*Cv], g_YL [2*Cv*Cv];
__device__ bf16 g_MH [2*Cv*Cv], g_ML [2*Cv*Cv];
__device__ float g_YF[2*Cv*Cv];
__device__ bf16 g_PcH[Cv*2*Cv], g_PcL[Cv*2*Cv];   // [P1||P2] along K (512 x 1024)
__device__ float g_part[2*Cv];
__device__ float g_rn[2];

// ================= helpers =================
__device__ __forceinline__ uint32_t smem_to_u32(const void* p) {
    uint32_t a;
    asm("{ .reg .u64 t; cvta.to.shared.u64 t, %1; cvt.u32.u64 %0, t; }" : "=r"(a) : "l"(p));
    return a;
}
__device__ __forceinline__ void split2(float x, bf16& h, bf16& l) {
    h = __float2bfloat16(x);
    l = __float2bfloat16(x - __bfloat162float(h));
}
__device__ __forceinline__ uint32_t pk2(bf16 a, bf16 b) {
    __nv_bfloat162 t; t.x = a; t.y = b;
    return *(uint32_t*)&t;
}
__device__ __forceinline__ void up2(uint32_t u, float& a, float& b) {
    __nv_bfloat162 t = *(__nv_bfloat162*)&u;
    a = __bfloat162float(t.x); b = __bfloat162float(t.y);
}
__device__ __forceinline__ void ldsm4(uint32_t (&r)[4], uint32_t addr) {
    asm volatile("ldmatrix.sync.aligned.m8n8.x4.shared.b16 {%0,%1,%2,%3}, [%4];"
        : "=r"(r[0]), "=r"(r[1]), "=r"(r[2]), "=r"(r[3]) : "r"(addr));
}
__device__ __forceinline__ void mma16816(float (&d)[4], const uint32_t (&a)[4],
                                         uint32_t b0, uint32_t b1) {
    asm volatile("mma.sync.aligned.m16n8k16.row.col.f32.bf16.bf16.f32 "
        "{%0,%1,%2,%3}, {%4,%5,%6,%7}, {%8,%9}, {%0,%1,%2,%3};"
        : "+f"(d[0]), "+f"(d[1]), "+f"(d[2]), "+f"(d[3])
        : "r"(a[0]), "r"(a[1]), "r"(a[2]), "r"(a[3]), "r"(b0), "r"(b1));
}
__device__ __forceinline__ void cp_async16(uint32_t so, const void* gp) {
    asm volatile("cp.async.cg.shared.global [%0], [%1], 16;" :: "r"(so), "l"(gp) : "memory");
}
#define CP_COMMIT() asm volatile("cp.async.commit_group;" ::: "memory")
#define CP_WAIT(n)  asm volatile("cp.async.wait_group %0;" :: "n"(n) : "memory")

// ================= mma.sync split-bf16 GEMM: C = alpha*A@B^T (+beta*add +diag*I) =====
// A: [M,K] bf16 hi/lo (K ranges split across Ah(k<K1)/Ah2(k>=K1), pitch lda).
// B: [N,K] bf16 hi/lo, pitch ldb. 3 passes hh+lh+hl interleaved with ldsm.
// CTA tile BMxBN, 8 warps in WR x (8/WR) grid. K-chunk 32, 3-stage cp.async
// pipeline, ONE __syncthreads per iteration (WAIT -> sync -> issue c+2 -> compute c).
// BM=256,BN=64,WR=4 maximizes arithmetic intensity (L2-traffic bound fix).
// grid.z batches: A/B/out/add advance by zA/zB/zOut/zAdd; rows offset by mskip.
// Optional transposed output (outTH/outTL) staged through smem (for polar Xt).
struct GA {
    const bf16 *Ah, *Al, *Ah2, *Al2, *Bh, *Bl;
    int M, N, K, K1, lda, ldb, mskip;
    long zA, zB;
};
struct TEpi {
    float alpha, beta, diag;
    const float* add; long zAdd;
    int gelu;
    float* outF; bf16 *outH, *outL; long zOut;
    bf16 *outTH, *outTL;     // transposed bf16 split output (square, pitch N)
};

template<int BM, int BN, int WR, int OCC>
__global__ __launch_bounds__(256, OCC)
void mma_gemm(GA g, TEpi e)
{
    constexpr int WC = 8/WR;               // warp cols
    constexpr int MF = BM/(16*WR);         // 16-row A frags per warp
    constexpr int NF = (BN/WC)/8;          // 8-col B frags per warp
    constexpr int NB = NF/2;
    static_assert(MF >= 1 && NB >= 1, "tile too small");
    constexpr int ASZA = BM*64;            // A operand tile (BM rows x 32 k x 2B)
    constexpr int ASZB = BN*64;            // B operand tile
    constexpr int BUF = 2*ASZA + 2*ASZB;
    extern __shared__ char smem[];
    const uint32_t sb = smem_to_u32(smem);
    const int tid  = threadIdx.x;
    const int lane = tid & 31;
    const int wid  = tid >> 5;
    const int wm   = wid % WR;
    const int wn   = wid / WR;
    const int m0 = g.mskip + blockIdx.y * BM;
    const int n0 = blockIdx.x * BN;
    const int bz = blockIdx.z;
    const int NC = g.K / 32;

    const bf16 *Ah = g.Ah + bz*g.zA,  *Al = g.Al + bz*g.zA;
    const bf16 *Ah2 = g.Ah2 + bz*g.zA, *Al2 = g.Al2 + bz*g.zA;
    const bf16 *Bh = g.Bh + bz*g.zB,  *Bl = g.Bl + bz*g.zB;

    // precomputed per-(ks,frag) smem offsets within a stage buffer
    int aOff[2][MF], bOff[2][NB];
    {
        const int aKb = (lane >> 4) * 16;
#pragma unroll
        for (int mf = 0; mf < MF; mf++) {
            int r = wm * (BM/WR) + mf * 16 + (lane & 15);
            int base = (r >> 1) * 128, po = (r & 1) * 64, xm = ((r >> 1) & 7) << 4;
#pragma unroll
            for (int ks = 0; ks < 2; ks++)
                aOff[ks][mf] = base + ((po + ks * 32 + aKb) ^ xm);
        }
        const int bKb = ((lane >> 3) & 1) * 16;
#pragma unroll
        for (int nb = 0; nb < NB; nb++) {
            int r = wn * (BN/WC) + nb * 16 + ((lane >> 4) << 3) + (lane & 7);
            int base = (r >> 1) * 128, po = (r & 1) * 64, xm = ((r >> 1) & 7) << 4;
#pragma unroll
            for (int ks = 0; ks < 2; ks++)
                bOff[ks][nb] = base + ((po + ks * 32 + bKb) ^ xm);
        }
    }

    float acc[MF][NF][4];
#pragma unroll
    for (int i = 0; i < MF; i++)
#pragma unroll
        for (int j = 0; j < NF; j++)
#pragma unroll
            for (int t = 0; t < 4; t++) acc[i][j][t] = 0.f;

    auto loadChunk = [&](int c) {
        const long cofs = (long)c * 32;
        const int st = c % 3;
        const bf16* AHc = Ah; const bf16* ALc = Al;
        long acol = cofs;
        if (cofs >= g.K1) { AHc = Ah2; ALc = Al2; acol = cofs - g.K1; }
        constexpr int TVA = BM * 4;     // 16B vectors per A tile
        constexpr int TVB = BN * 4;
        constexpr int NVEC = 2*TVA + 2*TVB;
#pragma unroll
        for (int t = 0; t < NVEC/256; t++) {
            int u = tid + t * 256;
            const bf16* base;
            int row, seg, sofs;
            if (u < TVA)            { base = AHc; row = u >> 2;          seg = u & 3;        sofs = 0;           }
            else if (u < 2*TVA)     { base = ALc; row = (u-TVA) >> 2;    seg = (u-TVA) & 3;  sofs = ASZA;        }
            else if (u < 2*TVA+TVB) { base = Bh;  row = (u-2*TVA) >> 2;  seg = (u-2*TVA) & 3; sofs = 2*ASZA;     }
            else                    { base = Bl;  row = (u-2*TVA-TVB) >> 2; seg = (u-2*TVA-TVB) & 3; sofs = 2*ASZA+ASZB; }
            const bf16* gp;
            if (sofs < 2*ASZA) gp = base + (long)(m0 + row) * g.lda + acol;
            else               gp = base + (long)(n0 + row) * g.ldb + cofs;
            gp += seg * 8;
            int j = row >> 1, p = row & 1;
            uint32_t so = sb + st * BUF + sofs + j * 128
                        + ((p * 64 + seg * 16) ^ ((j & 7) << 4));
            cp_async16(so, gp);
        }
        CP_COMMIT();
    };

    loadChunk(0);
    if (NC > 1) loadChunk(1);

    for (int c = 0; c < NC; c++) {
        if (c + 1 < NC) CP_WAIT(1);
        else            CP_WAIT(0);
        __syncthreads();
        if (c + 2 < NC) loadChunk(c + 2);

        const uint32_t bufB = sb + (c % 3) * BUF;
#pragma unroll
        for (int ks = 0; ks < 2; ks++) {
            uint32_t afH[MF][4], bfH[NB][4];
#pragma unroll
            for (int mf = 0; mf < MF; mf++)
                ldsm4(afH[mf], bufB + aOff[ks][mf]);
#pragma unroll
            for (int nb = 0; nb < NB; nb++)
                ldsm4(bfH[nb], bufB + 2*ASZA + bOff[ks][nb]);
            // pass hh
#pragma unroll
            for (int mf = 0; mf < MF; mf++)
#pragma unroll
                for (int nf = 0; nf < NF; nf++)
                    mma16816(acc[mf][nf], afH[mf], bfH[nf>>1][(nf&1)*2], bfH[nf>>1][(nf&1)*2+1]);
            // pass lh (afL loaded now; bfH still live)
            {
                uint32_t afL[MF][4];
#pragma unroll
                for (int mf = 0; mf < MF; mf++)
                    ldsm4(afL[mf], bufB + ASZA + aOff[ks][mf]);
#pragma unroll
                for (int mf = 0; mf < MF; mf++)
#pragma unroll
                    for (int nf = 0; nf < NF; nf++)
                        mma16816(acc[mf][nf], afL[mf], bfH[nf>>1][(nf&1)*2], bfH[nf>>1][(nf&1)*2+1]);
            }
            // pass hl (bfL loaded now; afH still live, afL/bfH dead)
            {
                uint32_t bfL[NB][4];
#pragma unroll
                for (int nb = 0; nb < NB; nb++)
                    ldsm4(bfL[nb], bufB + 2*ASZA + ASZB + bOff[ks][nb]);
#pragma unroll
                for (int mf = 0; mf < MF; mf++)
#pragma unroll
                    for (int nf = 0; nf < NF; nf++)
                        mma16816(acc[mf][nf], afH[mf], bfL[nf>>1][(nf&1)*2], bfL[nf>>1][(nf&1)*2+1]);
            }
        }
    }
    __syncthreads();    // all warps done with smem before epilogue staging reuses it

    // ---- epilogue ----
    float* outF = e.outF ? e.outF + bz*e.zOut : (float*)0;
    bf16*  outH = e.outH ? e.outH + bz*e.zOut : (bf16*)0;
    bf16*  outL = e.outL ? e.outL + bz*e.zOut : (bf16*)0;
    const float* add = e.add ? e.add + bz*e.zAdd : (const float*)0;
    bf16* sH = (bf16*)smem;                    // transposed staging [BM][BN+1]
    bf16* sL = sH + BM*(BN+1);
    const int rl = lane >> 2;
    const int cl = (lane & 3) * 2;
#pragma unroll
    for (int mf = 0; mf < MF; mf++) {
#pragma unroll
        for (int nf = 0; nf < NF; nf++) {
            int lc = wn * (BN/WC) + nf * 8 + cl;
            int c0 = n0 + lc;
#pragma unroll
            for (int half = 0; half < 2; half++) {
                int lr = wm * (BM/WR) + mf * 16 + rl + half * 8;
                int row = m0 + lr;
                long ofs = (long)row * g.N + c0;
                float f0 = e.alpha * acc[mf][nf][half*2];
                float f1 = e.alpha * acc[mf][nf][half*2 + 1];
                if (add) {
                    float2 ra = *(const float2*)(add + ofs);
                    f0 += e.beta * ra.x; f1 += e.beta * ra.y;
                }
                if (e.diag != 0.f) {
                    if (row == c0)     f0 += e.diag;
                    if (row == c0 + 1) f1 += e.diag;
                }
                if (e.gelu) {
                    f0 = 0.5f * f0 * (1.f + erff(f0 * 0.70710678118654752f));
                    f1 = 0.5f * f1 * (1.f + erff(f1 * 0.70710678118654752f));
                }
                if (outF)
                    *(float2*)(outF + ofs) = make_float2(f0, f1);
                if (outH || e.outTH) {
                    bf16 h0, h1, l0, l1;
                    split2(f0, h0, l0);
                    split2(f1, h1, l1);
                    if (outH) {
                        *(uint32_t*)(outH + ofs) = pk2(h0, h1);
                        *(uint32_t*)(outL + ofs) = pk2(l0, l1);
                    }
                    if (e.outTH) {
                        sH[lr*(BN+1) + lc] = h0; sH[lr*(BN+1) + lc + 1] = h1;
                        sL[lr*(BN+1) + lc] = l0; sL[lr*(BN+1) + lc + 1] = l1;
                    }
                }
            }
        }
    }
    if (e.outTH) {
        __syncthreads();
        bf16* outTH = e.outTH + bz*e.zOut;
        bf16* outTL = e.outTL + bz*e.zOut;
#pragma unroll
        for (int it = 0; it < (BM*BN)/256; it++) {
            int idx = tid + it * 256;
            int j = idx / BM;        // col of X = row of Xt
            int i = idx % BM;        // row of X
            long o = (long)(n0 + j) * g.N + m0 + i;
            outTH[o] = sH[i*(BN+1) + j];
            outTL[o] = sL[i*(BN+1) + j];
        }
    }
}

// ---------------- elementwise / reduction kernels ----------------
__global__ void ln_kernel(const float* __restrict__ x, const float* __restrict__ w,
                          bf16* __restrict__ oh, bf16* __restrict__ ol)
{
    const int r = blockIdx.x, tid = threadIdx.x;
    float4 f = ((const float4*)(x + (long)r*Cv))[tid];
    float s = f.x+f.y+f.z+f.w;
    float q = f.x*f.x+f.y*f.y+f.z*f.z+f.w*f.w;
    __shared__ float shs[4], shq[4];
#pragma unroll
    for (int off=16; off>0; off>>=1) {
        s += __shfl_down_sync(0xffffffffu, s, off);
        q += __shfl_down_sync(0xffffffffu, q, off);
    }
    if ((tid&31)==0) { shs[tid>>5]=s; shq[tid>>5]=q; }
    __syncthreads();
    float S = shs[0]+shs[1]+shs[2]+shs[3];
    float Q = shq[0]+shq[1]+shq[2]+shq[3];
    float mean = S*(1.f/Cv);
    float var  = Q*(1.f/Cv) - mean*mean;
    float inv  = rsqrtf(var + 1e-5f);
    float4 wf = ((const float4*)w)[tid];
    float o0=(f.x-mean)*inv*wf.x, o1=(f.y-mean)*inv*wf.y;
    float o2=(f.z-mean)*inv*wf.z, o3=(f.w-mean)*inv*wf.w;
    bf16 h0,h1,h2,h3,l0,l1,l2,l3;
    split2(o0,h0,l0); split2(o1,h1,l1); split2(o2,h2,l2); split2(o3,h3,l3);
    long ofs = (long)r*Cv + tid*4;
    uint2 uh; uh.x=pk2(h0,h1); uh.y=pk2(h2,h3);
    uint2 ul; ul.x=pk2(l0,l1); ul.y=pk2(l2,l3);
    *(uint2*)(oh+ofs)=uh; *(uint2*)(ol+ofs)=ul;
}

// in-place scan combine: q[t] <- rms(z[t]) for t >= d. grid (Tv - d, Bv).
__global__ void pscan_combine(const float* __restrict__ z,
                              bf16* __restrict__ qH, bf16* __restrict__ qL,
                              int d)
{
    const int t = d + blockIdx.x;
    const int r = blockIdx.y * Tv + t;
    const int tid = threadIdx.x;
    long ofs = (long)r*Cv + tid*4;
    float4 f = *(const float4*)(z+ofs);
    float q = f.x*f.x+f.y*f.y+f.z*f.z+f.w*f.w;
    __shared__ float shq[4];
#pragma unroll
    for (int off=16; off>0; off>>=1) q += __shfl_down_sync(0xffffffffu, q, off);
    if ((tid&31)==0) shq[tid>>5]=q;
    __syncthreads();
    float Q = shq[0]+shq[1]+shq[2]+shq[3];
    float sc = rsqrtf(Q*(1.f/Cv) + 1e-6f);
    float o0=f.x*sc, o1=f.y*sc, o2=f.z*sc, o3=f.w*sc;
    bf16 h0,h1,h2,h3,l0,l1,l2,l3;
    split2(o0,h0,l0); split2(o1,h1,l1); split2(o2,h2,l2); split2(o3,h3,l3);
    uint2 uh; uh.x=pk2(h0,h1); uh.y=pk2(h2,h3);
    uint2 ul; ul.x=pk2(l0,l1); ul.y=pk2(l2,l3);
    *(uint2*)(qH+ofs)=uh; *(uint2*)(qL+ofs)=ul;
}

// h = split(q * v) with q,v reconstructed from bf16 pairs
__global__ void mul_split(const bf16* __restrict__ qH, const bf16* __restrict__ qL,
                          const bf16* __restrict__ vH, const bf16* __restrict__ vL,
                          bf16* __restrict__ H, bf16* __restrict__ L)
{
    long i = ((long)blockIdx.x*256 + threadIdx.x)*4;
    uint2 a = *(const uint2*)(qH+i), b = *(const uint2*)(qL+i);
    uint2 c = *(const uint2*)(vH+i), d = *(const uint2*)(vL+i);
    float q0,q1,q2,q3,ql0,ql1,ql2,ql3,v0,v1,v2,v3,vl0,vl1,vl2,vl3;
    up2(a.x,q0,q1); up2(a.y,q2,q3); up2(b.x,ql0,ql1); up2(b.y,ql2,ql3);
    up2(c.x,v0,v1); up2(c.y,v2,v3); up2(d.x,vl0,vl1); up2(d.y,vl2,vl3);
    float o0=(q0+ql0)*(v0+vl0), o1=(q1+ql1)*(v1+vl1);
    float o2=(q2+ql2)*(v2+vl2), o3=(q3+ql3)*(v3+vl3);
    bf16 h0,h1,h2,h3,l0,l1,l2,l3;
    split2(o0,h0,l0); split2(o1,h1,l1); split2(o2,h2,l2); split2(o3,h3,l3);
    uint2 uh; uh.x=pk2(h0,h1); uh.y=pk2(h2,h3);
    uint2 ul; ul.x=pk2(l0,l1); ul.y=pk2(l2,l3);
    *(uint2*)(H+i)=uh; *(uint2*)(L+i)=ul;
}

// all five weight splits in one launch
__global__ void wsplit5(const float* __restrict__ Wq, const float* __restrict__ Wv,
                        const float* __restrict__ Wo, const float* __restrict__ Wfc,
                        const float* __restrict__ Wpr,
                        bf16* WqH, bf16* WqL, bf16* WvH, bf16* WvL,
                        bf16* WoH, bf16* WoL, bf16* WfcH, bf16* WfcL,
                        bf16* WprH, bf16* WprL)
{
    const int S = Cv*Cv;
    long i = (long)blockIdx.x*256 + threadIdx.x;   // over 11*S
    const float* W; bf16 *H, *L; long j;
    if      (i < S)       { W=Wq;  H=WqH;  L=WqL;  j=i; }
    else if (i < 2L*S)    { W=Wv;  H=WvH;  L=WvL;  j=i-S; }
    else if (i < 3L*S)    { W=Wo;  H=WoH;  L=WoL;  j=i-2L*S; }
    else if (i < 7L*S)    { W=Wfc; H=WfcH; L=WfcL; j=i-3L*S; }
    else                  { W=Wpr; H=WprH; L=WprL; j=i-7L*S; }
    float x = W[j];
    bf16 h, l; split2(x, h, l);
    H[j] = h; L[j] = l;
}

__global__ void frob1(const float* __restrict__ W1, const float* __restrict__ W2,
                      float* __restrict__ part)
{
    const int row = blockIdx.x, mat = blockIdx.y, tid = threadIdx.x;
    const float* W = mat ? W2 : W1;
    float4 f = ((const float4*)(W + (long)row*Cv))[tid];
    float q = f.x*f.x+f.y*f.y+f.z*f.z+f.w*f.w;
    __shared__ float shq[4];
#pragma unroll
    for (int off=16; off>0; off>>=1) q += __shfl_down_sync(0xffffffffu, q, off);
    if ((tid&31)==0) shq[tid>>5]=q;
    __syncthreads();
    if (tid==0) part[mat*Cv + row] = shq[0]+shq[1]+shq[2]+shq[3];
}

__global__ void frob2(const float* __restrict__ part, float* __restrict__ rn)
{
    const int mat = blockIdx.x, tid = threadIdx.x;
    __shared__ float sh[256];
    sh[tid] = part[mat*Cv + tid] + part[mat*Cv + tid + 256];
    __syncthreads();
    for (int off=128; off>0; off>>=1) {
        if (tid<off) sh[tid] += sh[tid+off];
        __syncthreads();
    }
    if (tid==0) rn[mat] = rsqrtf(sh[0]);
}

// X = W * rn, split to H/L, plus transposed copies. grid (16,16,2), block (32,8).
__global__ void split_tr_init(const float* __restrict__ W1, const float* __restrict__ W2,
                              const float* __restrict__ rn,
                              bf16* XH, bf16* XL, bf16* XtH, bf16* XtL)
{
    __shared__ float t[32][33];
    const int mat = blockIdx.z;
    const float* W = mat ? W2 : W1;
    const float s = rn[mat];
    const int r0 = blockIdx.y*32, c0 = blockIdx.x*32;
    const int tx = threadIdx.x, ty = threadIdx.y;
    const long mo = (long)mat*Sm;
#pragma unroll
    for (int i = 0; i < 4; i++) {
        int rr = ty + i*8;
        t[rr][tx] = W[(long)(r0+rr)*Cv + c0+tx] * s;
    }
    __syncthreads();
#pragma unroll
    for (int i = 0; i < 4; i++) {
        int rr = ty + i*8;
        bf16 h, l;
        split2(t[rr][tx], h, l);
        XH[mo + (long)(r0+rr)*Cv + c0+tx] = h;
        XL[mo + (long)(r0+rr)*Cv + c0+tx] = l;
        split2(t[tx][rr], h, l);
        XtH[mo + (long)(c0+rr)*Cv + r0+tx] = h;
        XtL[mo + (long)(c0+rr)*Cv + r0+tx] = l;
    }
}

// Pc[n, 0:512] = P1[n,:], Pc[n, 512:1024] = P2[n,:]
__global__ void packP(const bf16* __restrict__ XH, const bf16* __restrict__ XL,
                      bf16* __restrict__ PcH, bf16* __restrict__ PcL)
{
    int idx = blockIdx.x*256 + threadIdx.x;     // over 512*1024
    int n = idx >> 10, k = idx & 1023;
    long src = (k < 512) ? ((long)n*Cv + k) : (Sm + (long)n*Cv + (k-512));
    PcH[idx] = XH[src];
    PcL[idx] = XL[src];
}

// ---------------- host ----------------
static inline GA mkga(const bf16* Ah, const bf16* Al, const bf16* Bh, const bf16* Bl,
                      int M, int N, int K, int lda, int ldb, long zA = 0, long zB = 0)
{
    GA g; g.Ah=Ah; g.Al=Al; g.Ah2=Ah; g.Al2=Al; g.Bh=Bh; g.Bl=Bl;
    g.M=M; g.N=N; g.K=K; g.K1=K; g.lda=lda; g.ldb=ldb; g.mskip=0; g.zA=zA; g.zB=zB;
    return g;
}
static inline TEpi te()
{
    TEpi e; e.alpha=1.f; e.beta=1.f; e.diag=0.f; e.add=0; e.zAdd=0;
    e.gelu=0; e.outF=0; e.outH=0; e.outL=0; e.zOut=0; e.outTH=0; e.outTL=0;
    return e;
}

#define SMBIG (3*(2*256*64 + 2*64*64))       // 122880: 256x64 tiles, 3 stages
#define SMP   (3*(2*32*64 + 2*64*64))        // 36864: polar 32x64 tiles

extern "C" void kernel_launch(void* const* d_in, const int* in_sizes, int n_in,
                              void* d_out, int out_size)
{
    const float* x   = (const float*)d_in[0];
    const float* ln1 = (const float*)d_in[1];
    const float* Wq  = (const float*)d_in[2];
    const float* Wv  = (const float*)d_in[3];
    const float* Wo  = (const float*)d_in[4];
    // d_in[5] = identity : mathematically unused (rows computed from it are discarded)
    const float* Wp1 = (const float*)d_in[6];
    const float* Wp2 = (const float*)d_in[7];
    const float* ln2 = (const float*)d_in[8];
    const float* Wfc = (const float*)d_in[9];
    const float* Wpr = (const float*)d_in[10];
    float* out = (float*)d_out;

    cudaFuncSetAttribute(mma_gemm<256,64,4,1>, cudaFuncAttributeMaxDynamicSharedMemorySize, SMBIG);
    cudaFuncSetAttribute(mma_gemm<32,64,2,3>,  cudaFuncAttributeMaxDynamicSharedMemorySize, SMP);

    // streams: sP = polar chain, sM = main prep; both forked off the capture
    // origin stream and joined before the scan.
    static cudaStream_t sP = 0, sM = 0;
    static cudaEvent_t evF = 0, evJ = 0, evM = 0;
    if (!sP) {
        cudaStreamCreateWithFlags(&sP, cudaStreamNonBlocking);
        cudaStreamCreateWithFlags(&sM, cudaStreamNonBlocking);
        cudaEventCreateWithFlags(&evF, cudaEventDisableTiming);
        cudaEventCreateWithFlags(&evJ, cudaEventDisableTiming);
        cudaEventCreateWithFlags(&evM, cudaEventDisableTiming);
    }

    bf16 *qH,*qL,*vH,*vL,*hH,*hL,*fcH,*fcL;
    bf16 *WqH,*WqL,*WvH,*WvL,*WoH,*WoL,*WfcH,*WfcL,*WprH,*WprL;
    bf16 *XaH,*XaL,*XbH,*XbL,*XtH,*XtL,*YH,*YL,*MH,*ML,*PcH,*PcL;
    float *z,*YF,*part,*rn;
    cudaGetSymbolAddress((void**)&qH, g_qH);   cudaGetSymbolAddress((void**)&qL, g_qL);
    cudaGetSymbolAddress((void**)&vH, g_vH);   cudaGetSymbolAddress((void**)&vL, g_vL);
    cudaGetSymbolAddress((void**)&hH, g_hH);   cudaGetSymbolAddress((void**)&hL, g_hL);
    cudaGetSymbolAddress((void**)&fcH, g_fcH); cudaGetSymbolAddress((void**)&fcL, g_fcL);
    cudaGetSymbolAddress((void**)&WqH, g_WqH); cudaGetSymbolAddress((void**)&WqL, g_WqL);
    cudaGetSymbolAddress((void**)&WvH, g_WvH); cudaGetSymbolAddress((void**)&WvL, g_WvL);
    cudaGetSymbolAddress((void**)&WoH, g_WoH); cudaGetSymbolAddress((void**)&WoL, g_WoL);
    cudaGetSymbolAddress((void**)&WfcH,g_WfcH); cudaGetSymbolAddress((void**)&WfcL,g_WfcL);
    cudaGetSymbolAddress((void**)&WprH,g_WprH); cudaGetSymbolAddress((void**)&WprL,g_WprL);
    cudaGetSymbolAddress((void**)&XaH, g_XaH); cudaGetSymbolAddress((void**)&XaL, g_XaL);
    cudaGetSymbolAddress((void**)&XbH, g_XbH); cudaGetSymbolAddress((void**)&XbL, g_XbL);
    cudaGetSymbolAddress((void**)&XtH, g_XtH); cudaGetSymbolAddress((void**)&XtL, g_XtL);
    cudaGetSymbolAddress((void**)&YH,  g_YH);  cudaGetSymbolAddress((void**)&YL,  g_YL);
    cudaGetSymbolAddress((void**)&MH,  g_MH);  cudaGetSymbolAddress((void**)&ML,  g_ML);
    cudaGetSymbolAddress((void**)&PcH, g_PcH); cudaGetSymbolAddress((void**)&PcL, g_PcL);
    cudaGetSymbolAddress((void**)&z,   g_z);
    cudaGetSymbolAddress((void**)&YF,  g_YF);
    cudaGetSymbolAddress((void**)&part,g_part);
    cudaGetSymbolAddress((void**)&rn,  g_rn);

    // ---- fork ----
    cudaEventRecord(evF, 0);
    cudaStreamWaitEvent(sP, evF, 0);
    cudaStreamWaitEvent(sM, evF, 0);

    {   // polar factors via Muon-quintic + Newton-Schulz on tensor cores (stream sP)
        frob1<<<dim3(Cv,2),128,0,sP>>>(Wp1, Wp2, part);
        frob2<<<2,256,0,sP>>>(part, rn);
        split_tr_init<<<dim3(16,16,2),dim3(32,8),0,sP>>>(Wp1, Wp2, rn, XaH, XaL, XtH, XtL);

        const dim3 gp(Cv/64, Cv/32, 2);     // (8,16,2) = 256 CTAs, 32x64 tiles
        for (int it = 0; it < 9; ++it) {
            // Y = Xt @ Xt^T  (= X^T X, symmetric)
            GA g1 = mkga(XtH, XtL, XtH, XtL, Cv, Cv, Cv, Cv, Cv, Sm, Sm);
            TEpi e1 = te(); e1.outF = YF; e1.outH = YH; e1.outL = YL; e1.zOut = Sm;
            mma_gemm<32,64,2,3><<<gp,256,SMP,sP>>>(g1, e1);
            // M = 2.0315*Y@Y^T - 4.7750*Y + 3.4445*I  (symmetric)
            GA g2 = mkga(YH, YL, YH, YL, Cv, Cv, Cv, Cv, Cv, Sm, Sm);
            TEpi e2 = te(); e2.alpha = 2.0315f; e2.add = YF; e2.zAdd = Sm;
            e2.beta = -4.7750f; e2.diag = 3.4445f; e2.outH = MH; e2.outL = ML; e2.zOut = Sm;
            mma_gemm<32,64,2,3><<<gp,256,SMP,sP>>>(g2, e2);
            // X' = X @ M^T (= X M, M symmetric); epilogue also emits Xt'
            GA g3 = mkga(XaH, XaL, MH, ML, Cv, Cv, Cv, Cv, Cv, Sm, Sm);
            TEpi e3 = te(); e3.outH = XbH; e3.outL = XbL; e3.zOut = Sm;
            e3.outTH = XtH; e3.outTL = XtL;
            mma_gemm<32,64,2,3><<<gp,256,SMP,sP>>>(g3, e3);
            bf16* t;
            t = XaH; XaH = XbH; XbH = t;
            t = XaL; XaL = XbL; XbL = t;
        }
        for (int it = 0; it < 4; ++it) {
            // G = -0.5*Xt@Xt^T + 1.5I  (symmetric)
            GA g1 = mkga(XtH, XtL, XtH, XtL, Cv, Cv, Cv, Cv, Cv, Sm, Sm);
            TEpi e1 = te(); e1.alpha = -0.5f; e1.diag = 1.5f;
            e1.outH = MH; e1.outL = ML; e1.zOut = Sm;
            mma_gemm<32,64,2,3><<<gp,256,SMP,sP>>>(g1, e1);
            // X' = X @ G^T; epilogue also emits Xt'
            GA g2 = mkga(XaH, XaL, MH, ML, Cv, Cv, Cv, Cv, Cv, Sm, Sm);
            TEpi e2 = te(); e2.outH = XbH; e2.outL = XbL; e2.zOut = Sm;
            e2.outTH = XtH; e2.outTL = XtL;
            mma_gemm<32,64,2,3><<<gp,256,SMP,sP>>>(g2, e2);
            bf16* t;
            t = XaH; XaH = XbH; XbH = t;
            t = XaL; XaL = XbL; XbL = t;
        }
        packP<<<(Cv*2*Cv)/256,256,0,sP>>>(XaH, XaL, PcH, PcL);
        cudaEventRecord(evJ, sP);
    }

    {   // main prep: weight splits + ln + q/v GEMMs (stream sM, concurrent w/ polar)
        wsplit5<<<(11*Cv*Cv)/256,256,0,sM>>>(Wq, Wv, Wo, Wfc, Wpr,
            WqH, WqL, WvH, WvL, WoH, WoL, WfcH, WfcL, WprH, WprL);
        ln_kernel<<<Rv,128,0,sM>>>(x, ln1, hH, hL);
        GA gq = mkga(hH, hL, WqH, WqL, Rv, Cv, Cv, Cv, Cv);
        TEpi eq = te(); eq.outH = qH + GUARDE; eq.outL = qL + GUARDE;
        mma_gemm<256,64,4,1><<<dim3(Cv/64, Rv/256), 256, SMBIG, sM>>>(gq, eq);
        GA gv = mkga(hH, hL, WvH, WvL, Rv, Cv, Cv, Cv, Cv);
        TEpi ev = te(); ev.outH = vH; ev.outL = vL;
        mma_gemm<256,64,4,1><<<dim3(Cv/64, Rv/256), 256, SMBIG, sM>>>(gv, ev);
        cudaEventRecord(evM, sM);
    }

    // ---- join: scan needs Pc (sP) and q (sM) ----
    cudaStreamWaitEvent(0, evJ, 0);
    cudaStreamWaitEvent(0, evM, 0);

    for (int d = 1; d < Tv; d <<= 1) {
        const int mskip = d & ~255;          // whole 256-row tiles with t<d skipped
        // z = qshift @ P1^T + q @ P2^T : single GEMM, K=1024
        // chunks k<512 read q[t-d] (guard zeros / stale rows, discarded), k>=512 read q[t]
        GA gs = mkga(qH + GUARDE, qL + GUARDE, PcH, PcL, Rv, Cv, 2*Cv, Cv, 2*Cv);
        gs.Ah = qH + GUARDE - (long)d*Cv;
        gs.Al = qL + GUARDE - (long)d*Cv;
        gs.K1 = Cv;
        gs.mskip = mskip;
        gs.zA = (long)Tv*Cv;                  // batch stride (rows)
        TEpi es = te(); es.outF = z; es.zOut = (long)Tv*Cv;
        mma_gemm<256,64,4,1><<<dim3(Cv/64, (Tv-mskip)/256, Bv), 256, SMBIG>>>(gs, es);
        pscan_combine<<<dim3(Tv-d, Bv),128>>>(z, qH + GUARDE, qL + GUARDE, d);
    }

    // x1 = x + (q*v) @ Wo^T   (into d_out)
    mul_split<<<(Rv*Cv/4)/256,256>>>(qH + GUARDE, qL + GUARDE, vH, vL, hH, hL);
    {
        GA go = mkga(hH, hL, WoH, WoL, Rv, Cv, Cv, Cv, Cv);
        TEpi er = te(); er.add = x; er.outF = out;
        mma_gemm<256,64,4,1><<<dim3(Cv/64, Rv/256), 256, SMBIG>>>(go, er);
    }

    // ---- MLP branch ----
    ln_kernel<<<Rv,128>>>(out, ln2, hH, hL);
    {
        GA gf = mkga(hH, hL, WfcH, WfcL, Rv, Fv, Cv, Cv, Cv);
        TEpi eg = te(); eg.gelu = 1; eg.outH = fcH; eg.outL = fcL;
        mma_gemm<256,64,4,1><<<dim3(Fv/64, Rv/256), 256, SMBIG>>>(gf, eg);
        GA gr = mkga(fcH, fcL, WprH, WprL, Rv, Cv, Fv, Fv, Fv);
        TEpi er2 = te(); er2.add = out; er2.outF = out;
        mma_gemm<256,64,4,1><<<dim3(Cv/64, Rv/256), 256, SMBIG>>>(gr, er2);
    }
}

// round 13
// speedup vs baseline: 1.1613x; 1.1613x over previous
#include <cuda_runtime.h>
#include <cuda_bf16.h>
#include <math.h>
#include <stdint.h>

#define Bv 4
#define Tv 4096
#define Cv 512
#define Rv (Bv*Tv)            // 16384 rows
#define Fv (4*Cv)             // 2048
#define GUARDE (2048*Cv)      // guard rows (zero-init) for shifted scan operand
#define Sm ((long)Cv*Cv)

typedef __nv_bfloat16 bf16;

// ---------------- static device scratch (zero-initialized) ----------------
__device__ bf16 g_qH[GUARDE + Rv*Cv];
__device__ bf16 g_qL[GUARDE + Rv*Cv];
__device__ bf16 g_vH[Rv*Cv], g_vL[Rv*Cv];
__device__ bf16 g_zH[Rv*Cv], g_zL[Rv*Cv];
__device__ bf16 g_hH[Rv*Cv], g_hL[Rv*Cv];
__device__ bf16 g_fcH[Rv*Fv], g_fcL[Rv*Fv];
// weight splits
__device__ bf16 g_WqH[Cv*Cv], g_WqL[Cv*Cv];
__device__ bf16 g_WvH[Cv*Cv], g_WvL[Cv*Cv];
__device__ bf16 g_WoH[Cv*Cv], g_WoL[Cv*Cv];
__device__ bf16 g_WfcH[Fv*Cv], g_WfcL[Fv*Cv];
__device__ bf16 g_WprH[Cv*Fv], g_WprL[Cv*Fv];
// polar scratch (x2 matrices, batched)
__device__ bf16 g_XaH[2*Cv*Cv], g_XaL[2*Cv*Cv];
__device__ bf16 g_XbH[2*Cv*Cv], g_XbL[2*Cv*Cv];
__device__ bf16 g_XtH[2*Cv*Cv], g_XtL[2*Cv*Cv];
__device__ bf16 g_YH [2*Cv*Cv], g_YL [2*Cv*Cv];
__device__ bf16 g_MH [2*Cv*Cv], g_ML [2*Cv*Cv];
__device__ float g_YF[2*Cv*Cv];
__device__ bf16 g_PcH[Cv*2*Cv], g_PcL[Cv*2*Cv];   // [P1||P2] along K (512 x 1024)
__device__ float g_part[2*Cv];
__device__ float g_rn[2];

// ================= helpers =================
__device__ __forceinline__ uint32_t smem_to_u32(const void* p) {
    uint32_t a;
    asm("{ .reg .u64 t; cvta.to.shared.u64 t, %1; cvt.u32.u64 %0, t; }" : "=r"(a) : "l"(p));
    return a;
}
__device__ __forceinline__ void split2(float x, bf16& h, bf16& l) {
    h = __float2bfloat16(x);
    l = __float2bfloat16(x - __bfloat162float(h));
}
__device__ __forceinline__ uint32_t pk2(bf16 a, bf16 b) {
    __nv_bfloat162 t; t.x = a; t.y = b;
    return *(uint32_t*)&t;
}
__device__ __forceinline__ void up2(uint32_t u, float& a, float& b) {
    __nv_bfloat162 t = *(__nv_bfloat162*)&u;
    a = __bfloat162float(t.x); b = __bfloat162float(t.y);
}
__device__ __forceinline__ void ldsm4(uint32_t (&r)[4], uint32_t addr) {
    asm volatile("ldmatrix.sync.aligned.m8n8.x4.shared.b16 {%0,%1,%2,%3}, [%4];"
        : "=r"(r[0]), "=r"(r[1]), "=r"(r[2]), "=r"(r[3]) : "r"(addr));
}
__device__ __forceinline__ void mma16816(float (&d)[4], const uint32_t (&a)[4],
                                         uint32_t b0, uint32_t b1) {
    asm volatile("mma.sync.aligned.m16n8k16.row.col.f32.bf16.bf16.f32 "
        "{%0,%1,%2,%3}, {%4,%5,%6,%7}, {%8,%9}, {%0,%1,%2,%3};"
        : "+f"(d[0]), "+f"(d[1]), "+f"(d[2]), "+f"(d[3])
        : "r"(a[0]), "r"(a[1]), "r"(a[2]), "r"(a[3]), "r"(b0), "r"(b1));
}
__device__ __forceinline__ void cp_async16(uint32_t so, const void* gp) {
    asm volatile("cp.async.cg.shared.global [%0], [%1], 16;" :: "r"(so), "l"(gp) : "memory");
}
#define CP_COMMIT() asm volatile("cp.async.commit_group;" ::: "memory")
#define CP_WAIT(n)  asm volatile("cp.async.wait_group %0;" :: "n"(n) : "memory")

// ================= mma.sync split-bf16 GEMM: C = alpha*A@B^T (+beta*add +diag*I) =====
// A: [M,K] bf16 hi/lo (K ranges split across Ah(k<K1)/Ah2(k>=K1), pitch lda).
// B: [N,K] bf16 hi/lo, pitch ldb. 3 passes hh+lh+hl interleaved with ldsm.
// CTA tile BMxBN, 8 warps in WR x (8/WR) grid. K-chunk 32, 3-stage cp.async
// pipeline, ONE __syncthreads per iteration (WAIT -> sync -> issue c+2 -> compute c).
// 128x128 @ OCC=2 is the measured optimum (two CTAs/SM cover each other's stalls).
// grid.z batches: A/B/out/add advance by zA/zB/zOut/zAdd; rows offset by mskip.
// Optional transposed output (outTH/outTL) staged through smem (for polar Xt).
struct GA {
    const bf16 *Ah, *Al, *Ah2, *Al2, *Bh, *Bl;
    int M, N, K, K1, lda, ldb, mskip;
    long zA, zB;
};
struct TEpi {
    float alpha, beta, diag;
    const float* add; long zAdd;
    int gelu;
    float* outF; bf16 *outH, *outL; long zOut;
    bf16 *outTH, *outTL;     // transposed bf16 split output (square, pitch N)
};

template<int BM, int BN, int WR, int OCC>
__global__ __launch_bounds__(256, OCC)
void mma_gemm(GA g, TEpi e)
{
    constexpr int WC = 8/WR;               // warp cols
    constexpr int MF = BM/(16*WR);         // 16-row A frags per warp
    constexpr int NF = (BN/WC)/8;          // 8-col B frags per warp
    constexpr int NB = NF/2;
    static_assert(MF >= 1 && NB >= 1, "tile too small");
    constexpr int ASZA = BM*64;            // A operand tile (BM rows x 32 k x 2B)
    constexpr int ASZB = BN*64;            // B operand tile
    constexpr int BUF = 2*ASZA + 2*ASZB;
    extern __shared__ char smem[];
    const uint32_t sb = smem_to_u32(smem);
    const int tid  = threadIdx.x;
    const int lane = tid & 31;
    const int wid  = tid >> 5;
    const int wm   = wid % WR;
    const int wn   = wid / WR;
    const int m0 = g.mskip + blockIdx.y * BM;
    const int n0 = blockIdx.x * BN;
    const int bz = blockIdx.z;
    const int NC = g.K / 32;

    const bf16 *Ah = g.Ah + bz*g.zA,  *Al = g.Al + bz*g.zA;
    const bf16 *Ah2 = g.Ah2 + bz*g.zA, *Al2 = g.Al2 + bz*g.zA;
    const bf16 *Bh = g.Bh + bz*g.zB,  *Bl = g.Bl + bz*g.zB;

    // precomputed per-(ks,frag) smem offsets within a stage buffer
    int aOff[2][MF], bOff[2][NB];
    {
        const int aKb = (lane >> 4) * 16;
#pragma unroll
        for (int mf = 0; mf < MF; mf++) {
            int r = wm * (BM/WR) + mf * 16 + (lane & 15);
            int base = (r >> 1) * 128, po = (r & 1) * 64, xm = ((r >> 1) & 7) << 4;
#pragma unroll
            for (int ks = 0; ks < 2; ks++)
                aOff[ks][mf] = base + ((po + ks * 32 + aKb) ^ xm);
        }
        const int bKb = ((lane >> 3) & 1) * 16;
#pragma unroll
        for (int nb = 0; nb < NB; nb++) {
            int r = wn * (BN/WC) + nb * 16 + ((lane >> 4) << 3) + (lane & 7);
            int base = (r >> 1) * 128, po = (r & 1) * 64, xm = ((r >> 1) & 7) << 4;
#pragma unroll
            for (int ks = 0; ks < 2; ks++)
                bOff[ks][nb] = base + ((po + ks * 32 + bKb) ^ xm);
        }
    }

    float acc[MF][NF][4];
#pragma unroll
    for (int i = 0; i < MF; i++)
#pragma unroll
        for (int j = 0; j < NF; j++)
#pragma unroll
            for (int t = 0; t < 4; t++) acc[i][j][t] = 0.f;

    auto loadChunk = [&](int c) {
        const long cofs = (long)c * 32;
        const int st = c % 3;
        const bf16* AHc = Ah; const bf16* ALc = Al;
        long acol = cofs;
        if (cofs >= g.K1) { AHc = Ah2; ALc = Al2; acol = cofs - g.K1; }
        constexpr int TVA = BM * 4;     // 16B vectors per A tile
        constexpr int TVB = BN * 4;
        constexpr int NVEC = 2*TVA + 2*TVB;
#pragma unroll
        for (int t = 0; t < NVEC/256; t++) {
            int u = tid + t * 256;
            const bf16* base;
            int row, seg, sofs;
            if (u < TVA)            { base = AHc; row = u >> 2;          seg = u & 3;        sofs = 0;           }
            else if (u < 2*TVA)     { base = ALc; row = (u-TVA) >> 2;    seg = (u-TVA) & 3;  sofs = ASZA;        }
            else if (u < 2*TVA+TVB) { base = Bh;  row = (u-2*TVA) >> 2;  seg = (u-2*TVA) & 3; sofs = 2*ASZA;     }
            else                    { base = Bl;  row = (u-2*TVA-TVB) >> 2; seg = (u-2*TVA-TVB) & 3; sofs = 2*ASZA+ASZB; }
            const bf16* gp;
            if (sofs < 2*ASZA) gp = base + (long)(m0 + row) * g.lda + acol;
            else               gp = base + (long)(n0 + row) * g.ldb + cofs;
            gp += seg * 8;
            int j = row >> 1, p = row & 1;
            uint32_t so = sb + st * BUF + sofs + j * 128
                        + ((p * 64 + seg * 16) ^ ((j & 7) << 4));
            cp_async16(so, gp);
        }
        CP_COMMIT();
    };

    loadChunk(0);
    if (NC > 1) loadChunk(1);

    for (int c = 0; c < NC; c++) {
        if (c + 1 < NC) CP_WAIT(1);
        else            CP_WAIT(0);
        __syncthreads();
        if (c + 2 < NC) loadChunk(c + 2);

        const uint32_t bufB = sb + (c % 3) * BUF;
#pragma unroll
        for (int ks = 0; ks < 2; ks++) {
            uint32_t afH[MF][4], bfH[NB][4];
#pragma unroll
            for (int mf = 0; mf < MF; mf++)
                ldsm4(afH[mf], bufB + aOff[ks][mf]);
#pragma unroll
            for (int nb = 0; nb < NB; nb++)
                ldsm4(bfH[nb], bufB + 2*ASZA + bOff[ks][nb]);
            // pass hh
#pragma unroll
            for (int mf = 0; mf < MF; mf++)
#pragma unroll
                for (int nf = 0; nf < NF; nf++)
                    mma16816(acc[mf][nf], afH[mf], bfH[nf>>1][(nf&1)*2], bfH[nf>>1][(nf&1)*2+1]);
            // pass lh (afL loaded now; bfH still live)
            {
                uint32_t afL[MF][4];
#pragma unroll
                for (int mf = 0; mf < MF; mf++)
                    ldsm4(afL[mf], bufB + ASZA + aOff[ks][mf]);
#pragma unroll
                for (int mf = 0; mf < MF; mf++)
#pragma unroll
                    for (int nf = 0; nf < NF; nf++)
                        mma16816(acc[mf][nf], afL[mf], bfH[nf>>1][(nf&1)*2], bfH[nf>>1][(nf&1)*2+1]);
            }
            // pass hl (bfL loaded now; afH still live, afL/bfH dead)
            {
                uint32_t bfL[NB][4];
#pragma unroll
                for (int nb = 0; nb < NB; nb++)
                    ldsm4(bfL[nb], bufB + 2*ASZA + ASZB + bOff[ks][nb]);
#pragma unroll
                for (int mf = 0; mf < MF; mf++)
#pragma unroll
                    for (int nf = 0; nf < NF; nf++)
                        mma16816(acc[mf][nf], afH[mf], bfL[nf>>1][(nf&1)*2], bfL[nf>>1][(nf&1)*2+1]);
            }
        }
    }
    __syncthreads();    // all warps done with smem before epilogue staging reuses it

    // ---- epilogue ----
    float* outF = e.outF ? e.outF + bz*e.zOut : (float*)0;
    bf16*  outH = e.outH ? e.outH + bz*e.zOut : (bf16*)0;
    bf16*  outL = e.outL ? e.outL + bz*e.zOut : (bf16*)0;
    const float* add = e.add ? e.add + bz*e.zAdd : (const float*)0;
    bf16* sH = (bf16*)smem;                    // transposed staging [BM][BN+1]
    bf16* sL = sH + BM*(BN+1);
    const int rl = lane >> 2;
    const int cl = (lane & 3) * 2;
#pragma unroll
    for (int mf = 0; mf < MF; mf++) {
#pragma unroll
        for (int nf = 0; nf < NF; nf++) {
            int lc = wn * (BN/WC) + nf * 8 + cl;
            int c0 = n0 + lc;
#pragma unroll
            for (int half = 0; half < 2; half++) {
                int lr = wm * (BM/WR) + mf * 16 + rl + half * 8;
                int row = m0 + lr;
                long ofs = (long)row * g.N + c0;
                float f0 = e.alpha * acc[mf][nf][half*2];
                float f1 = e.alpha * acc[mf][nf][half*2 + 1];
                if (add) {
                    float2 ra = *(const float2*)(add + ofs);
                    f0 += e.beta * ra.x; f1 += e.beta * ra.y;
                }
                if (e.diag != 0.f) {
                    if (row == c0)     f0 += e.diag;
                    if (row == c0 + 1) f1 += e.diag;
                }
                if (e.gelu) {
                    f0 = 0.5f * f0 * (1.f + erff(f0 * 0.70710678118654752f));
                    f1 = 0.5f * f1 * (1.f + erff(f1 * 0.70710678118654752f));
                }
                if (outF)
                    *(float2*)(outF + ofs) = make_float2(f0, f1);
                if (outH || e.outTH) {
                    bf16 h0, h1, l0, l1;
                    split2(f0, h0, l0);
                    split2(f1, h1, l1);
                    if (outH) {
                        *(uint32_t*)(outH + ofs) = pk2(h0, h1);
                        *(uint32_t*)(outL + ofs) = pk2(l0, l1);
                    }
                    if (e.outTH) {
                        sH[lr*(BN+1) + lc] = h0; sH[lr*(BN+1) + lc + 1] = h1;
                        sL[lr*(BN+1) + lc] = l0; sL[lr*(BN+1) + lc + 1] = l1;
                    }
                }
            }
        }
    }
    if (e.outTH) {
        __syncthreads();
        bf16* outTH = e.outTH + bz*e.zOut;
        bf16* outTL = e.outTL + bz*e.zOut;
#pragma unroll
        for (int it = 0; it < (BM*BN)/256; it++) {
            int idx = tid + it * 256;
            int j = idx / BM;        // col of X = row of Xt
            int i = idx % BM;        // row of X
            long o = (long)(n0 + j) * g.N + m0 + i;
            outTH[o] = sH[i*(BN+1) + j];
            outTL[o] = sL[i*(BN+1) + j];
        }
    }
}

// ---------------- elementwise / reduction kernels ----------------
__global__ void ln_kernel(const float* __restrict__ x, const float* __restrict__ w,
                          bf16* __restrict__ oh, bf16* __restrict__ ol)
{
    const int r = blockIdx.x, tid = threadIdx.x;
    float4 f = ((const float4*)(x + (long)r*Cv))[tid];
    float s = f.x+f.y+f.z+f.w;
    float q = f.x*f.x+f.y*f.y+f.z*f.z+f.w*f.w;
    __shared__ float shs[4], shq[4];
#pragma unroll
    for (int off=16; off>0; off>>=1) {
        s += __shfl_down_sync(0xffffffffu, s, off);
        q += __shfl_down_sync(0xffffffffu, q, off);
    }
    if ((tid&31)==0) { shs[tid>>5]=s; shq[tid>>5]=q; }
    __syncthreads();
    float S = shs[0]+shs[1]+shs[2]+shs[3];
    float Q = shq[0]+shq[1]+shq[2]+shq[3];
    float mean = S*(1.f/Cv);
    float var  = Q*(1.f/Cv) - mean*mean;
    float inv  = rsqrtf(var + 1e-5f);
    float4 wf = ((const float4*)w)[tid];
    float o0=(f.x-mean)*inv*wf.x, o1=(f.y-mean)*inv*wf.y;
    float o2=(f.z-mean)*inv*wf.z, o3=(f.w-mean)*inv*wf.w;
    bf16 h0,h1,h2,h3,l0,l1,l2,l3;
    split2(o0,h0,l0); split2(o1,h1,l1); split2(o2,h2,l2); split2(o3,h3,l3);
    long ofs = (long)r*Cv + tid*4;
    uint2 uh; uh.x=pk2(h0,h1); uh.y=pk2(h2,h3);
    uint2 ul; ul.x=pk2(l0,l1); ul.y=pk2(l2,l3);
    *(uint2*)(oh+ofs)=uh; *(uint2*)(ol+ofs)=ul;
}

// in-place scan combine: q[t] <- rms(z[t]) for t >= d; z given as bf16 hi/lo pairs.
// grid (Tv - d, Bv).
__global__ void pscan_combine(const bf16* __restrict__ zH, const bf16* __restrict__ zL,
                              bf16* __restrict__ qH, bf16* __restrict__ qL,
                              int d)
{
    const int t = d + blockIdx.x;
    const int r = blockIdx.y * Tv + t;
    const int tid = threadIdx.x;
    long ofs = (long)r*Cv + tid*4;
    uint2 a = *(const uint2*)(zH+ofs);
    uint2 b = *(const uint2*)(zL+ofs);
    float zh0,zh1,zh2,zh3, zl0,zl1,zl2,zl3;
    up2(a.x,zh0,zh1); up2(a.y,zh2,zh3);
    up2(b.x,zl0,zl1); up2(b.y,zl2,zl3);
    float f0=zh0+zl0, f1=zh1+zl1, f2=zh2+zl2, f3=zh3+zl3;
    float q = f0*f0+f1*f1+f2*f2+f3*f3;
    __shared__ float shq[4];
#pragma unroll
    for (int off=16; off>0; off>>=1) q += __shfl_down_sync(0xffffffffu, q, off);
    if ((tid&31)==0) shq[tid>>5]=q;
    __syncthreads();
    float Q = shq[0]+shq[1]+shq[2]+shq[3];
    float sc = rsqrtf(Q*(1.f/Cv) + 1e-6f);
    float o0=f0*sc, o1=f1*sc, o2=f2*sc, o3=f3*sc;
    bf16 h0,h1,h2,h3,l0,l1,l2,l3;
    split2(o0,h0,l0); split2(o1,h1,l1); split2(o2,h2,l2); split2(o3,h3,l3);
    uint2 uh; uh.x=pk2(h0,h1); uh.y=pk2(h2,h3);
    uint2 ul; ul.x=pk2(l0,l1); ul.y=pk2(l2,l3);
    *(uint2*)(qH+ofs)=uh; *(uint2*)(qL+ofs)=ul;
}

// h = split(q * v) with q,v reconstructed from bf16 pairs
__global__ void mul_split(const bf16* __restrict__ qH, const bf16* __restrict__ qL,
                          const bf16* __restrict__ vH, const bf16* __restrict__ vL,
                          bf16* __restrict__ H, bf16* __restrict__ L)
{
    long i = ((long)blockIdx.x*256 + threadIdx.x)*4;
    uint2 a = *(const uint2*)(qH+i), b = *(const uint2*)(qL+i);
    uint2 c = *(const uint2*)(vH+i), d = *(const uint2*)(vL+i);
    float q0,q1,q2,q3,ql0,ql1,ql2,ql3,v0,v1,v2,v3,vl0,vl1,vl2,vl3;
    up2(a.x,q0,q1); up2(a.y,q2,q3); up2(b.x,ql0,ql1); up2(b.y,ql2,ql3);
    up2(c.x,v0,v1); up2(c.y,v2,v3); up2(d.x,vl0,vl1); up2(d.y,vl2,vl3);
    float o0=(q0+ql0)*(v0+vl0), o1=(q1+ql1)*(v1+vl1);
    float o2=(q2+ql2)*(v2+vl2), o3=(q3+ql3)*(v3+vl3);
    bf16 h0,h1,h2,h3,l0,l1,l2,l3;
    split2(o0,h0,l0); split2(o1,h1,l1); split2(o2,h2,l2); split2(o3,h3,l3);
    uint2 uh; uh.x=pk2(h0,h1); uh.y=pk2(h2,h3);
    uint2 ul; ul.x=pk2(l0,l1); ul.y=pk2(l2,l3);
    *(uint2*)(H+i)=uh; *(uint2*)(L+i)=ul;
}

// all five weight splits in one launch
__global__ void wsplit5(const float* __restrict__ Wq, const float* __restrict__ Wv,
                        const float* __restrict__ Wo, const float* __restrict__ Wfc,
                        const float* __restrict__ Wpr,
                        bf16* WqH, bf16* WqL, bf16* WvH, bf16* WvL,
                        bf16* WoH, bf16* WoL, bf16* WfcH, bf16* WfcL,
                        bf16* WprH, bf16* WprL)
{
    const int S = Cv*Cv;
    long i = (long)blockIdx.x*256 + threadIdx.x;   // over 11*S
    const float* W; bf16 *H, *L; long j;
    if      (i < S)       { W=Wq;  H=WqH;  L=WqL;  j=i; }
    else if (i < 2L*S)    { W=Wv;  H=WvH;  L=WvL;  j=i-S; }
    else if (i < 3L*S)    { W=Wo;  H=WoH;  L=WoL;  j=i-2L*S; }
    else if (i < 7L*S)    { W=Wfc; H=WfcH; L=WfcL; j=i-3L*S; }
    else                  { W=Wpr; H=WprH; L=WprL; j=i-7L*S; }
    float x = W[j];
    bf16 h, l; split2(x, h, l);
    H[j] = h; L[j] = l;
}

__global__ void frob1(const float* __restrict__ W1, const float* __restrict__ W2,
                      float* __restrict__ part)
{
    const int row = blockIdx.x, mat = blockIdx.y, tid = threadIdx.x;
    const float* W = mat ? W2 : W1;
    float4 f = ((const float4*)(W + (long)row*Cv))[tid];
    float q = f.x*f.x+f.y*f.y+f.z*f.z+f.w*f.w;
    __shared__ float shq[4];
#pragma unroll
    for (int off=16; off>0; off>>=1) q += __shfl_down_sync(0xffffffffu, q, off);
    if ((tid&31)==0) shq[tid>>5]=q;
    __syncthreads();
    if (tid==0) part[mat*Cv + row] = shq[0]+shq[1]+shq[2]+shq[3];
}

__global__ void frob2(const float* __restrict__ part, float* __restrict__ rn)
{
    const int mat = blockIdx.x, tid = threadIdx.x;
    __shared__ float sh[256];
    sh[tid] = part[mat*Cv + tid] + part[mat*Cv + tid + 256];
    __syncthreads();
    for (int off=128; off>0; off>>=1) {
        if (tid<off) sh[tid] += sh[tid+off];
        __syncthreads();
    }
    if (tid==0) rn[mat] = rsqrtf(sh[0]);
}

// X = W * rn, split to H/L, plus transposed copies. grid (16,16,2), block (32,8).
__global__ void split_tr_init(const float* __restrict__ W1, const float* __restrict__ W2,
                              const float* __restrict__ rn,
                              bf16* XH, bf16* XL, bf16* XtH, bf16* XtL)
{
    __shared__ float t[32][33];
    const int mat = blockIdx.z;
    const float* W = mat ? W2 : W1;
    const float s = rn[mat];
    const int r0 = blockIdx.y*32, c0 = blockIdx.x*32;
    const int tx = threadIdx.x, ty = threadIdx.y;
    const long mo = (long)mat*Sm;
#pragma unroll
    for (int i = 0; i < 4; i++) {
        int rr = ty + i*8;
        t[rr][tx] = W[(long)(r0+rr)*Cv + c0+tx] * s;
    }
    __syncthreads();
#pragma unroll
    for (int i = 0; i < 4; i++) {
        int rr = ty + i*8;
        bf16 h, l;
        split2(t[rr][tx], h, l);
        XH[mo + (long)(r0+rr)*Cv + c0+tx] = h;
        XL[mo + (long)(r0+rr)*Cv + c0+tx] = l;
        split2(t[tx][rr], h, l);
        XtH[mo + (long)(c0+rr)*Cv + r0+tx] = h;
        XtL[mo + (long)(c0+rr)*Cv + r0+tx] = l;
    }
}

// Pc[n, 0:512] = P1[n,:], Pc[n, 512:1024] = P2[n,:]
__global__ void packP(const bf16* __restrict__ XH, const bf16* __restrict__ XL,
                      bf16* __restrict__ PcH, bf16* __restrict__ PcL)
{
    int idx = blockIdx.x*256 + threadIdx.x;     // over 512*1024
    int n = idx >> 10, k = idx & 1023;
    long src = (k < 512) ? ((long)n*Cv + k) : (Sm + (long)n*Cv + (k-512));
    PcH[idx] = XH[src];
    PcL[idx] = XL[src];
}

// ---------------- host ----------------
static inline GA mkga(const bf16* Ah, const bf16* Al, const bf16* Bh, const bf16* Bl,
                      int M, int N, int K, int lda, int ldb, long zA = 0, long zB = 0)
{
    GA g; g.Ah=Ah; g.Al=Al; g.Ah2=Ah; g.Al2=Al; g.Bh=Bh; g.Bl=Bl;
    g.M=M; g.N=N; g.K=K; g.K1=K; g.lda=lda; g.ldb=ldb; g.mskip=0; g.zA=zA; g.zB=zB;
    return g;
}
static inline TEpi te()
{
    TEpi e; e.alpha=1.f; e.beta=1.f; e.diag=0.f; e.add=0; e.zAdd=0;
    e.gelu=0; e.outF=0; e.outH=0; e.outL=0; e.zOut=0; e.outTH=0; e.outTL=0;
    return e;
}

#define SM128 (3*4*128*64)                   // 98304: 128x128 tiles, 3 stages
#define SMP   (3*(2*32*64 + 2*64*64))        // 36864: polar 32x64 tiles

extern "C" void kernel_launch(void* const* d_in, const int* in_sizes, int n_in,
                              void* d_out, int out_size)
{
    const float* x   = (const float*)d_in[0];
    const float* ln1 = (const float*)d_in[1];
    const float* Wq  = (const float*)d_in[2];
    const float* Wv  = (const float*)d_in[3];
    const float* Wo  = (const float*)d_in[4];
    // d_in[5] = identity : mathematically unused (rows computed from it are discarded)
    const float* Wp1 = (const float*)d_in[6];
    const float* Wp2 = (const float*)d_in[7];
    const float* ln2 = (const float*)d_in[8];
    const float* Wfc = (const float*)d_in[9];
    const float* Wpr = (const float*)d_in[10];
    float* out = (float*)d_out;

    cudaFuncSetAttribute(mma_gemm<128,128,2,2>, cudaFuncAttributeMaxDynamicSharedMemorySize, SM128);
    cudaFuncSetAttribute(mma_gemm<32,64,2,3>,   cudaFuncAttributeMaxDynamicSharedMemorySize, SMP);

    // streams: sP = polar chain, sM = main prep; both forked off the capture
    // origin stream and joined before the scan.
    static cudaStream_t sP = 0, sM = 0;
    static cudaEvent_t evF = 0, evJ = 0, evM = 0;
    if (!sP) {
        cudaStreamCreateWithFlags(&sP, cudaStreamNonBlocking);
        cudaStreamCreateWithFlags(&sM, cudaStreamNonBlocking);
        cudaEventCreateWithFlags(&evF, cudaEventDisableTiming);
        cudaEventCreateWithFlags(&evJ, cudaEventDisableTiming);
        cudaEventCreateWithFlags(&evM, cudaEventDisableTiming);
    }

    bf16 *qH,*qL,*vH,*vL,*zH,*zL,*hH,*hL,*fcH,*fcL;
    bf16 *WqH,*WqL,*WvH,*WvL,*WoH,*WoL,*WfcH,*WfcL,*WprH,*WprL;
    bf16 *XaH,*XaL,*XbH,*XbL,*XtH,*XtL,*YH,*YL,*MH,*ML,*PcH,*PcL;
    float *YF,*part,*rn;
    cudaGetSymbolAddress((void**)&qH, g_qH);   cudaGetSymbolAddress((void**)&qL, g_qL);
    cudaGetSymbolAddress((void**)&vH, g_vH);   cudaGetSymbolAddress((void**)&vL, g_vL);
    cudaGetSymbolAddress((void**)&zH, g_zH);   cudaGetSymbolAddress((void**)&zL, g_zL);
    cudaGetSymbolAddress((void**)&hH, g_hH);   cudaGetSymbolAddress((void**)&hL, g_hL);
    cudaGetSymbolAddress((void**)&fcH, g_fcH); cudaGetSymbolAddress((void**)&fcL, g_fcL);
    cudaGetSymbolAddress((void**)&WqH, g_WqH); cudaGetSymbolAddress((void**)&WqL, g_WqL);
    cudaGetSymbolAddress((void**)&WvH, g_WvH); cudaGetSymbolAddress((void**)&WvL, g_WvL);
    cudaGetSymbolAddress((void**)&WoH, g_WoH); cudaGetSymbolAddress((void**)&WoL, g_WoL);
    cudaGetSymbolAddress((void**)&WfcH,g_WfcH); cudaGetSymbolAddress((void**)&WfcL,g_WfcL);
    cudaGetSymbolAddress((void**)&WprH,g_WprH); cudaGetSymbolAddress((void**)&WprL,g_WprL);
    cudaGetSymbolAddress((void**)&XaH, g_XaH); cudaGetSymbolAddress((void**)&XaL, g_XaL);
    cudaGetSymbolAddress((void**)&XbH, g_XbH); cudaGetSymbolAddress((void**)&XbL, g_XbL);
    cudaGetSymbolAddress((void**)&XtH, g_XtH); cudaGetSymbolAddress((void**)&XtL, g_XtL);
    cudaGetSymbolAddress((void**)&YH,  g_YH);  cudaGetSymbolAddress((void**)&YL,  g_YL);
    cudaGetSymbolAddress((void**)&MH,  g_MH);  cudaGetSymbolAddress((void**)&ML,  g_ML);
    cudaGetSymbolAddress((void**)&PcH, g_PcH); cudaGetSymbolAddress((void**)&PcL, g_PcL);
    cudaGetSymbolAddress((void**)&YF,  g_YF);
    cudaGetSymbolAddress((void**)&part,g_part);
    cudaGetSymbolAddress((void**)&rn,  g_rn);

    // ---- fork ----
    cudaEventRecord(evF, 0);
    cudaStreamWaitEvent(sP, evF, 0);
    cudaStreamWaitEvent(sM, evF, 0);

    {   // polar factors via Muon-quintic + Newton-Schulz on tensor cores (stream sP)
        frob1<<<dim3(Cv,2),128,0,sP>>>(Wp1, Wp2, part);
        frob2<<<2,256,0,sP>>>(part, rn);
        split_tr_init<<<dim3(16,16,2),dim3(32,8),0,sP>>>(Wp1, Wp2, rn, XaH, XaL, XtH, XtL);

        const dim3 gp(Cv/64, Cv/32, 2);     // (8,16,2) = 256 CTAs, 32x64 tiles
        for (int it = 0; it < 9; ++it) {
            // Y = Xt @ Xt^T  (= X^T X, symmetric)
            GA g1 = mkga(XtH, XtL, XtH, XtL, Cv, Cv, Cv, Cv, Cv, Sm, Sm);
            TEpi e1 = te(); e1.outF = YF; e1.outH = YH; e1.outL = YL; e1.zOut = Sm;
            mma_gemm<32,64,2,3><<<gp,256,SMP,sP>>>(g1, e1);
            // M = 2.0315*Y@Y^T - 4.7750*Y + 3.4445*I  (symmetric)
            GA g2 = mkga(YH, YL, YH, YL, Cv, Cv, Cv, Cv, Cv, Sm, Sm);
            TEpi e2 = te(); e2.alpha = 2.0315f; e2.add = YF; e2.zAdd = Sm;
            e2.beta = -4.7750f; e2.diag = 3.4445f; e2.outH = MH; e2.outL = ML; e2.zOut = Sm;
            mma_gemm<32,64,2,3><<<gp,256,SMP,sP>>>(g2, e2);
            // X' = X @ M^T (= X M, M symmetric); epilogue also emits Xt'
            GA g3 = mkga(XaH, XaL, MH, ML, Cv, Cv, Cv, Cv, Cv, Sm, Sm);
            TEpi e3 = te(); e3.outH = XbH; e3.outL = XbL; e3.zOut = Sm;
            e3.outTH = XtH; e3.outTL = XtL;
            mma_gemm<32,64,2,3><<<gp,256,SMP,sP>>>(g3, e3);
            bf16* t;
            t = XaH; XaH = XbH; XbH = t;
            t = XaL; XaL = XbL; XbL = t;
        }
        for (int it = 0; it < 4; ++it) {
            // G = -0.5*Xt@Xt^T + 1.5I  (symmetric)
            GA g1 = mkga(XtH, XtL, XtH, XtL, Cv, Cv, Cv, Cv, Cv, Sm, Sm);
            TEpi e1 = te(); e1.alpha = -0.5f; e1.diag = 1.5f;
            e1.outH = MH; e1.outL = ML; e1.zOut = Sm;
            mma_gemm<32,64,2,3><<<gp,256,SMP,sP>>>(g1, e1);
            // X' = X @ G^T; epilogue also emits Xt'
            GA g2 = mkga(XaH, XaL, MH, ML, Cv, Cv, Cv, Cv, Cv, Sm, Sm);
            TEpi e2 = te(); e2.outH = XbH; e2.outL = XbL; e2.zOut = Sm;
            e2.outTH = XtH; e2.outTL = XtL;
            mma_gemm<32,64,2,3><<<gp,256,SMP,sP>>>(g2, e2);
            bf16* t;
            t = XaH; XaH = XbH; XbH = t;
            t = XaL; XaL = XbL; XbL = t;
        }
        packP<<<(Cv*2*Cv)/256,256,0,sP>>>(XaH, XaL, PcH, PcL);
        cudaEventRecord(evJ, sP);
    }

    {   // main prep: weight splits + ln + q/v GEMMs (stream sM, concurrent w/ polar)
        wsplit5<<<(11*Cv*Cv)/256,256,0,sM>>>(Wq, Wv, Wo, Wfc, Wpr,
            WqH, WqL, WvH, WvL, WoH, WoL, WfcH, WfcL, WprH, WprL);
        ln_kernel<<<Rv,128,0,sM>>>(x, ln1, hH, hL);
        GA gq = mkga(hH, hL, WqH, WqL, Rv, Cv, Cv, Cv, Cv);
        TEpi eq = te(); eq.outH = qH + GUARDE; eq.outL = qL + GUARDE;
        mma_gemm<128,128,2,2><<<dim3(Cv/128, Rv/128), 256, SM128, sM>>>(gq, eq);
        GA gv = mkga(hH, hL, WvH, WvL, Rv, Cv, Cv, Cv, Cv);
        TEpi ev = te(); ev.outH = vH; ev.outL = vL;
        mma_gemm<128,128,2,2><<<dim3(Cv/128, Rv/128), 256, SM128, sM>>>(gv, ev);
        cudaEventRecord(evM, sM);
    }

    // ---- join: scan needs Pc (sP) and q (sM) ----
    cudaStreamWaitEvent(0, evJ, 0);
    cudaStreamWaitEvent(0, evM, 0);

    for (int d = 1; d < Tv; d <<= 1) {
        const int mskip = d & ~127;          // whole 128-row tiles with t<d skipped
        // z = qshift @ P1^T + q @ P2^T : single GEMM, K=1024, output split-bf16
        // chunks k<512 read q[t-d] (guard zeros / stale rows, discarded), k>=512 read q[t]
        GA gs = mkga(qH + GUARDE, qL + GUARDE, PcH, PcL, Rv, Cv, 2*Cv, Cv, 2*Cv);
        gs.Ah = qH + GUARDE - (long)d*Cv;
        gs.Al = qL + GUARDE - (long)d*Cv;
        gs.K1 = Cv;
        gs.mskip = mskip;
        gs.zA = (long)Tv*Cv;                  // batch stride (rows)
        TEpi es = te(); es.outH = zH; es.outL = zL; es.zOut = (long)Tv*Cv;
        mma_gemm<128,128,2,2><<<dim3(Cv/128, (Tv-mskip)/128, Bv), 256, SM128>>>(gs, es);
        pscan_combine<<<dim3(Tv-d, Bv),128>>>(zH, zL, qH + GUARDE, qL + GUARDE, d);
    }

    // x1 = x + (q*v) @ Wo^T   (into d_out)
    mul_split<<<(Rv*Cv/4)/256,256>>>(qH + GUARDE, qL + GUARDE, vH, vL, hH, hL);
    {
        GA go = mkga(hH, hL, WoH, WoL, Rv, Cv, Cv, Cv, Cv);
        TEpi er = te(); er.add = x; er.outF = out;
        mma_gemm<128,128,2,2><<<dim3(Cv/128, Rv/128), 256, SM128>>>(go, er);
    }

    // ---- MLP branch ----
    ln_kernel<<<Rv,128>>>(out, ln2, hH, hL);
    {
        GA gf = mkga(hH, hL, WfcH, WfcL, Rv, Fv, Cv, Cv, Cv);
        TEpi eg = te(); eg.gelu = 1; eg.outH = fcH; eg.outL = fcL;
        mma_gemm<128,128,2,2><<<dim3(Fv/128, Rv/128), 256, SM128>>>(gf, eg);
        GA gr = mkga(fcH, fcL, WprH, WprL, Rv, Cv, Fv, Fv, Fv);
        TEpi er2 = te(); er2.add = out; er2.outF = out;
        mma_gemm<128,128,2,2><<<dim3(Cv/128, Rv/128), 256, SM128>>>(gr, er2);
    }
}

// round 14
// speedup vs baseline: 1.1669x; 1.0048x over previous
#include <cuda_runtime.h>
#include <cuda_bf16.h>
#include <math.h>
#include <stdint.h>

#define Bv 4
#define Tv 4096
#define Cv 512
#define Rv (Bv*Tv)            // 16384 rows
#define Fv (4*Cv)             // 2048
#define GUARDE (2048*Cv)      // guard rows (zero-init) for shifted scan operand
#define Sm ((long)Cv*Cv)

typedef __nv_bfloat16 bf16;

// ---------------- static device scratch (zero-initialized) ----------------
__device__ bf16 g_qH[GUARDE + Rv*Cv];
__device__ bf16 g_qL[GUARDE + Rv*Cv];
__device__ bf16 g_vH[Rv*Cv], g_vL[Rv*Cv];
__device__ float g_z[Rv*Cv];
__device__ bf16 g_hH[Rv*Cv], g_hL[Rv*Cv];
__device__ bf16 g_fcH[Rv*Fv], g_fcL[Rv*Fv];
// weight splits
__device__ bf16 g_WqH[Cv*Cv], g_WqL[Cv*Cv];
__device__ bf16 g_WvH[Cv*Cv], g_WvL[Cv*Cv];
__device__ bf16 g_WoH[Cv*Cv], g_WoL[Cv*Cv];
__device__ bf16 g_WfcH[Fv*Cv], g_WfcL[Fv*Cv];
__device__ bf16 g_WprH[Cv*Fv], g_WprL[Cv*Fv];
// polar scratch (x2 matrices, batched)
__device__ bf16 g_XaH[2*Cv*Cv], g_XaL[2*Cv*Cv];
__device__ bf16 g_XbH[2*Cv*Cv], g_XbL[2*Cv*Cv];
__device__ bf16 g_XtH[2*Cv*Cv], g_XtL[2*Cv*Cv];
__device__ bf16 g_YH [2*Cv*Cv], g_YL [2*Cv*Cv];
__device__ bf16 g_MH [2*Cv*Cv], g_ML [2*Cv*Cv];
__device__ float g_YF[2*Cv*Cv];
__device__ bf16 g_PcH[Cv*2*Cv], g_PcL[Cv*2*Cv];   // [P1||P2] along K (512 x 1024)
__device__ float g_part[2*Cv];
__device__ float g_rn[2];

// ================= helpers =================
__device__ __forceinline__ uint32_t smem_to_u32(const void* p) {
    uint32_t a;
    asm("{ .reg .u64 t; cvta.to.shared.u64 t, %1; cvt.u32.u64 %0, t; }" : "=r"(a) : "l"(p));
    return a;
}
__device__ __forceinline__ void split2(float x, bf16& h, bf16& l) {
    h = __float2bfloat16(x);
    l = __float2bfloat16(x - __bfloat162float(h));
}
__device__ __forceinline__ uint32_t pk2(bf16 a, bf16 b) {
    __nv_bfloat162 t; t.x = a; t.y = b;
    return *(uint32_t*)&t;
}
__device__ __forceinline__ void up2(uint32_t u, float& a, float& b) {
    __nv_bfloat162 t = *(__nv_bfloat162*)&u;
    a = __bfloat162float(t.x); b = __bfloat162float(t.y);
}
__device__ __forceinline__ void ldsm4(uint32_t (&r)[4], uint32_t addr) {
    asm volatile("ldmatrix.sync.aligned.m8n8.x4.shared.b16 {%0,%1,%2,%3}, [%4];"
        : "=r"(r[0]), "=r"(r[1]), "=r"(r[2]), "=r"(r[3]) : "r"(addr));
}
__device__ __forceinline__ void mma16816(float (&d)[4], const uint32_t (&a)[4],
                                         uint32_t b0, uint32_t b1) {
    asm volatile("mma.sync.aligned.m16n8k16.row.col.f32.bf16.bf16.f32 "
        "{%0,%1,%2,%3}, {%4,%5,%6,%7}, {%8,%9}, {%0,%1,%2,%3};"
        : "+f"(d[0]), "+f"(d[1]), "+f"(d[2]), "+f"(d[3])
        : "r"(a[0]), "r"(a[1]), "r"(a[2]), "r"(a[3]), "r"(b0), "r"(b1));
}
__device__ __forceinline__ void cp_async16(uint32_t so, const void* gp) {
    asm volatile("cp.async.cg.shared.global [%0], [%1], 16;" :: "r"(so), "l"(gp) : "memory");
}
#define CP_COMMIT() asm volatile("cp.async.commit_group;" ::: "memory")
#define CP_WAIT(n)  asm volatile("cp.async.wait_group %0;" :: "n"(n) : "memory")

// ================= mma.sync split-bf16 GEMM: C = alpha*A@B^T (+beta*add +diag*I) =====
// A: [M,K] bf16 hi/lo (K ranges split across Ah(k<K1)/Ah2(k>=K1), pitch lda).
// B: [N,K] bf16 hi/lo, pitch ldb. 3 passes hh+lh+hl interleaved with ldsm.
// CTA tile BMxBN, 8 warps in WR x (8/WR) grid. K-chunk 32, NSTG-stage cp.async
// pipeline (NSTG-1 chunks in flight), ONE __syncthreads per iteration.
// 128x128 @ OCC=2/NSTG=3 is the measured big-GEMM optimum; the small-K polar
// GEMM uses NSTG=5 to amortize L2 latency over 4 in-flight chunks.
// grid.z batches: A/B/out/add advance by zA/zB/zOut/zAdd; rows offset by mskip.
// Optional transposed output (outTH/outTL) staged through smem (for polar Xt).
struct GA {
    const bf16 *Ah, *Al, *Ah2, *Al2, *Bh, *Bl;
    int M, N, K, K1, lda, ldb, mskip;
    long zA, zB;
};
struct TEpi {
    float alpha, beta, diag;
    const float* add; long zAdd;
    int gelu;
    float* outF; bf16 *outH, *outL; long zOut;
    bf16 *outTH, *outTL;     // transposed bf16 split output (square, pitch N)
};

template<int BM, int BN, int WR, int OCC, int NSTG>
__global__ __launch_bounds__(256, OCC)
void mma_gemm(GA g, TEpi e)
{
    constexpr int WC = 8/WR;               // warp cols
    constexpr int MF = BM/(16*WR);         // 16-row A frags per warp
    constexpr int NF = (BN/WC)/8;          // 8-col B frags per warp
    constexpr int NB = NF/2;
    static_assert(MF >= 1 && NB >= 1, "tile too small");
    constexpr int ASZA = BM*64;            // A operand tile (BM rows x 32 k x 2B)
    constexpr int ASZB = BN*64;            // B operand tile
    constexpr int BUF = 2*ASZA + 2*ASZB;
    extern __shared__ char smem[];
    const uint32_t sb = smem_to_u32(smem);
    const int tid  = threadIdx.x;
    const int lane = tid & 31;
    const int wid  = tid >> 5;
    const int wm   = wid % WR;
    const int wn   = wid / WR;
    const int m0 = g.mskip + blockIdx.y * BM;
    const int n0 = blockIdx.x * BN;
    const int bz = blockIdx.z;
    const int NC = g.K / 32;

    const bf16 *Ah = g.Ah + bz*g.zA,  *Al = g.Al + bz*g.zA;
    const bf16 *Ah2 = g.Ah2 + bz*g.zA, *Al2 = g.Al2 + bz*g.zA;
    const bf16 *Bh = g.Bh + bz*g.zB,  *Bl = g.Bl + bz*g.zB;

    // precomputed per-(ks,frag) smem offsets within a stage buffer
    int aOff[2][MF], bOff[2][NB];
    {
        const int aKb = (lane >> 4) * 16;
#pragma unroll
        for (int mf = 0; mf < MF; mf++) {
            int r = wm * (BM/WR) + mf * 16 + (lane & 15);
            int base = (r >> 1) * 128, po = (r & 1) * 64, xm = ((r >> 1) & 7) << 4;
#pragma unroll
            for (int ks = 0; ks < 2; ks++)
                aOff[ks][mf] = base + ((po + ks * 32 + aKb) ^ xm);
        }
        const int bKb = ((lane >> 3) & 1) * 16;
#pragma unroll
        for (int nb = 0; nb < NB; nb++) {
            int r = wn * (BN/WC) + nb * 16 + ((lane >> 4) << 3) + (lane & 7);
            int base = (r >> 1) * 128, po = (r & 1) * 64, xm = ((r >> 1) & 7) << 4;
#pragma unroll
            for (int ks = 0; ks < 2; ks++)
                bOff[ks][nb] = base + ((po + ks * 32 + bKb) ^ xm);
        }
    }

    float acc[MF][NF][4];
#pragma unroll
    for (int i = 0; i < MF; i++)
#pragma unroll
        for (int j = 0; j < NF; j++)
#pragma unroll
            for (int t = 0; t < 4; t++) acc[i][j][t] = 0.f;

    auto loadChunk = [&](int c) {
        const long cofs = (long)c * 32;
        const int st = c % NSTG;
        const bf16* AHc = Ah; const bf16* ALc = Al;
        long acol = cofs;
        if (cofs >= g.K1) { AHc = Ah2; ALc = Al2; acol = cofs - g.K1; }
        constexpr int TVA = BM * 4;     // 16B vectors per A tile
        constexpr int TVB = BN * 4;
        constexpr int NVEC = 2*TVA + 2*TVB;
#pragma unroll
        for (int t = 0; t < NVEC/256; t++) {
            int u = tid + t * 256;
            const bf16* base;
            int row, seg, sofs;
            if (u < TVA)            { base = AHc; row = u >> 2;          seg = u & 3;        sofs = 0;           }
            else if (u < 2*TVA)     { base = ALc; row = (u-TVA) >> 2;    seg = (u-TVA) & 3;  sofs = ASZA;        }
            else if (u < 2*TVA+TVB) { base = Bh;  row = (u-2*TVA) >> 2;  seg = (u-2*TVA) & 3; sofs = 2*ASZA;     }
            else                    { base = Bl;  row = (u-2*TVA-TVB) >> 2; seg = (u-2*TVA-TVB) & 3; sofs = 2*ASZA+ASZB; }
            const bf16* gp;
            if (sofs < 2*ASZA) gp = base + (long)(m0 + row) * g.lda + acol;
            else               gp = base + (long)(n0 + row) * g.ldb + cofs;
            gp += seg * 8;
            int j = row >> 1, p = row & 1;
            uint32_t so = sb + st * BUF + sofs + j * 128
                        + ((p * 64 + seg * 16) ^ ((j & 7) << 4));
            cp_async16(so, gp);
        }
        CP_COMMIT();
    };

    for (int i = 0; i < NSTG - 1 && i < NC; i++) loadChunk(i);

    for (int c = 0; c < NC; c++) {
        // wait until chunk c's group completes: after it, rem groups were issued
        int rem = NC - 1 - c;
        if (rem > NSTG - 2) rem = NSTG - 2;
        if (NSTG >= 5 && rem >= 3)      CP_WAIT(3);
        else if (NSTG >= 4 && rem >= 2) CP_WAIT(2);
        else if (rem >= 1)              CP_WAIT(1);
        else                            CP_WAIT(0);
        __syncthreads();
        if (c + NSTG - 1 < NC) loadChunk(c + NSTG - 1);

        const uint32_t bufB = sb + (c % NSTG) * BUF;
#pragma unroll
        for (int ks = 0; ks < 2; ks++) {
            uint32_t afH[MF][4], bfH[NB][4];
#pragma unroll
            for (int mf = 0; mf < MF; mf++)
                ldsm4(afH[mf], bufB + aOff[ks][mf]);
#pragma unroll
            for (int nb = 0; nb < NB; nb++)
                ldsm4(bfH[nb], bufB + 2*ASZA + bOff[ks][nb]);
            // pass hh
#pragma unroll
            for (int mf = 0; mf < MF; mf++)
#pragma unroll
                for (int nf = 0; nf < NF; nf++)
                    mma16816(acc[mf][nf], afH[mf], bfH[nf>>1][(nf&1)*2], bfH[nf>>1][(nf&1)*2+1]);
            // pass lh (afL loaded now; bfH still live)
            {
                uint32_t afL[MF][4];
#pragma unroll
                for (int mf = 0; mf < MF; mf++)
                    ldsm4(afL[mf], bufB + ASZA + aOff[ks][mf]);
#pragma unroll
                for (int mf = 0; mf < MF; mf++)
#pragma unroll
                    for (int nf = 0; nf < NF; nf++)
                        mma16816(acc[mf][nf], afL[mf], bfH[nf>>1][(nf&1)*2], bfH[nf>>1][(nf&1)*2+1]);
            }
            // pass hl (bfL loaded now; afH still live, afL/bfH dead)
            {
                uint32_t bfL[NB][4];
#pragma unroll
                for (int nb = 0; nb < NB; nb++)
                    ldsm4(bfL[nb], bufB + 2*ASZA + ASZB + bOff[ks][nb]);
#pragma unroll
                for (int mf = 0; mf < MF; mf++)
#pragma unroll
                    for (int nf = 0; nf < NF; nf++)
                        mma16816(acc[mf][nf], afH[mf], bfL[nf>>1][(nf&1)*2], bfL[nf>>1][(nf&1)*2+1]);
            }
        }
    }
    __syncthreads();    // all warps done with smem before epilogue staging reuses it

    // ---- epilogue ----
    float* outF = e.outF ? e.outF + bz*e.zOut : (float*)0;
    bf16*  outH = e.outH ? e.outH + bz*e.zOut : (bf16*)0;
    bf16*  outL = e.outL ? e.outL + bz*e.zOut : (bf16*)0;
    const float* add = e.add ? e.add + bz*e.zAdd : (const float*)0;
    bf16* sH = (bf16*)smem;                    // transposed staging [BM][BN+1]
    bf16* sL = sH + BM*(BN+1);
    const int rl = lane >> 2;
    const int cl = (lane & 3) * 2;
#pragma unroll
    for (int mf = 0; mf < MF; mf++) {
#pragma unroll
        for (int nf = 0; nf < NF; nf++) {
            int lc = wn * (BN/WC) + nf * 8 + cl;
            int c0 = n0 + lc;
#pragma unroll
            for (int half = 0; half < 2; half++) {
                int lr = wm * (BM/WR) + mf * 16 + rl + half * 8;
                int row = m0 + lr;
                long ofs = (long)row * g.N + c0;
                float f0 = e.alpha * acc[mf][nf][half*2];
                float f1 = e.alpha * acc[mf][nf][half*2 + 1];
                if (add) {
                    float2 ra = *(const float2*)(add + ofs);
                    f0 += e.beta * ra.x; f1 += e.beta * ra.y;
                }
                if (e.diag != 0.f) {
                    if (row == c0)     f0 += e.diag;
                    if (row == c0 + 1) f1 += e.diag;
                }
                if (e.gelu) {
                    f0 = 0.5f * f0 * (1.f + erff(f0 * 0.70710678118654752f));
                    f1 = 0.5f * f1 * (1.f + erff(f1 * 0.70710678118654752f));
                }
                if (outF)
                    *(float2*)(outF + ofs) = make_float2(f0, f1);
                if (outH || e.outTH) {
                    bf16 h0, h1, l0, l1;
                    split2(f0, h0, l0);
                    split2(f1, h1, l1);
                    if (outH) {
                        *(uint32_t*)(outH + ofs) = pk2(h0, h1);
                        *(uint32_t*)(outL + ofs) = pk2(l0, l1);
                    }
                    if (e.outTH) {
                        sH[lr*(BN+1) + lc] = h0; sH[lr*(BN+1) + lc + 1] = h1;
                        sL[lr*(BN+1) + lc] = l0; sL[lr*(BN+1) + lc + 1] = l1;
                    }
                }
            }
        }
    }
    if (e.outTH) {
        __syncthreads();
        bf16* outTH = e.outTH + bz*e.zOut;
        bf16* outTL = e.outTL + bz*e.zOut;
#pragma unroll
        for (int it = 0; it < (BM*BN)/256; it++) {
            int idx = tid + it * 256;
            int j = idx / BM;        // col of X = row of Xt
            int i = idx % BM;        // row of X
            long o = (long)(n0 + j) * g.N + m0 + i;
            outTH[o] = sH[i*(BN+1) + j];
            outTL[o] = sL[i*(BN+1) + j];
        }
    }
}

// ---------------- elementwise / reduction kernels ----------------
__global__ void ln_kernel(const float* __restrict__ x, const float* __restrict__ w,
                          bf16* __restrict__ oh, bf16* __restrict__ ol)
{
    const int r = blockIdx.x, tid = threadIdx.x;
    float4 f = ((const float4*)(x + (long)r*Cv))[tid];
    float s = f.x+f.y+f.z+f.w;
    float q = f.x*f.x+f.y*f.y+f.z*f.z+f.w*f.w;
    __shared__ float shs[4], shq[4];
#pragma unroll
    for (int off=16; off>0; off>>=1) {
        s += __shfl_down_sync(0xffffffffu, s, off);
        q += __shfl_down_sync(0xffffffffu, q, off);
    }
    if ((tid&31)==0) { shs[tid>>5]=s; shq[tid>>5]=q; }
    __syncthreads();
    float S = shs[0]+shs[1]+shs[2]+shs[3];
    float Q = shq[0]+shq[1]+shq[2]+shq[3];
    float mean = S*(1.f/Cv);
    float var  = Q*(1.f/Cv) - mean*mean;
    float inv  = rsqrtf(var + 1e-5f);
    float4 wf = ((const float4*)w)[tid];
    float o0=(f.x-mean)*inv*wf.x, o1=(f.y-mean)*inv*wf.y;
    float o2=(f.z-mean)*inv*wf.z, o3=(f.w-mean)*inv*wf.w;
    bf16 h0,h1,h2,h3,l0,l1,l2,l3;
    split2(o0,h0,l0); split2(o1,h1,l1); split2(o2,h2,l2); split2(o3,h3,l3);
    long ofs = (long)r*Cv + tid*4;
    uint2 uh; uh.x=pk2(h0,h1); uh.y=pk2(h2,h3);
    uint2 ul; ul.x=pk2(l0,l1); ul.y=pk2(l2,l3);
    *(uint2*)(oh+ofs)=uh; *(uint2*)(ol+ofs)=ul;
}

// in-place scan combine: q[t] <- rms(z[t]) for t >= d; 4 rows per 512-thr block.
// grid ((Tv-mskip)/4, Bv). Inactive rows (t<d) participate in barriers but don't store.
__global__ void pscan_combine(const float* __restrict__ z,
                              bf16* __restrict__ qH, bf16* __restrict__ qL,
                              int d, int mskip)
{
    const int grp = threadIdx.x >> 7;        // 0..3 row groups of 128 threads
    const int tid = threadIdx.x & 127;
    const int t = mskip + blockIdx.x * 4 + grp;
    const bool active = (t >= d);
    const int r = blockIdx.y * Tv + t;
    long ofs = (long)r*Cv + tid*4;
    float4 f = *(const float4*)(z+ofs);      // garbage if !active; discarded
    float q = f.x*f.x+f.y*f.y+f.z*f.z+f.w*f.w;
    __shared__ float shq[4][4];
#pragma unroll
    for (int off=16; off>0; off>>=1) q += __shfl_down_sync(0xffffffffu, q, off);
    if ((tid&31)==0) shq[grp][tid>>5]=q;
    __syncthreads();
    float Q = shq[grp][0]+shq[grp][1]+shq[grp][2]+shq[grp][3];
    float sc = rsqrtf(Q*(1.f/Cv) + 1e-6f);
    if (!active) return;
    float o0=f.x*sc, o1=f.y*sc, o2=f.z*sc, o3=f.w*sc;
    bf16 h0,h1,h2,h3,l0,l1,l2,l3;
    split2(o0,h0,l0); split2(o1,h1,l1); split2(o2,h2,l2); split2(o3,h3,l3);
    uint2 uh; uh.x=pk2(h0,h1); uh.y=pk2(h2,h3);
    uint2 ul; ul.x=pk2(l0,l1); ul.y=pk2(l2,l3);
    *(uint2*)(qH+ofs)=uh; *(uint2*)(qL+ofs)=ul;
}

// h = split(q * v) with q,v reconstructed from bf16 pairs
__global__ void mul_split(const bf16* __restrict__ qH, const bf16* __restrict__ qL,
                          const bf16* __restrict__ vH, const bf16* __restrict__ vL,
                          bf16* __restrict__ H, bf16* __restrict__ L)
{
    long i = ((long)blockIdx.x*256 + threadIdx.x)*4;
    uint2 a = *(const uint2*)(qH+i), b = *(const uint2*)(qL+i);
    uint2 c = *(const uint2*)(vH+i), d = *(const uint2*)(vL+i);
    float q0,q1,q2,q3,ql0,ql1,ql2,ql3,v0,v1,v2,v3,vl0,vl1,vl2,vl3;
    up2(a.x,q0,q1); up2(a.y,q2,q3); up2(b.x,ql0,ql1); up2(b.y,ql2,ql3);
    up2(c.x,v0,v1); up2(c.y,v2,v3); up2(d.x,vl0,vl1); up2(d.y,vl2,vl3);
    float o0=(q0+ql0)*(v0+vl0), o1=(q1+ql1)*(v1+vl1);
    float o2=(q2+ql2)*(v2+vl2), o3=(q3+ql3)*(v3+vl3);
    bf16 h0,h1,h2,h3,l0,l1,l2,l3;
    split2(o0,h0,l0); split2(o1,h1,l1); split2(o2,h2,l2); split2(o3,h3,l3);
    uint2 uh; uh.x=pk2(h0,h1); uh.y=pk2(h2,h3);
    uint2 ul; ul.x=pk2(l0,l1); ul.y=pk2(l2,l3);
    *(uint2*)(H+i)=uh; *(uint2*)(L+i)=ul;
}

// all five weight splits in one launch
__global__ void wsplit5(const float* __restrict__ Wq, const float* __restrict__ Wv,
                        const float* __restrict__ Wo, const float* __restrict__ Wfc,
                        const float* __restrict__ Wpr,
                        bf16* WqH, bf16* WqL, bf16* WvH, bf16* WvL,
                        bf16* WoH, bf16* WoL, bf16* WfcH, bf16* WfcL,
                        bf16* WprH, bf16* WprL)
{
    const int S = Cv*Cv;
    long i = (long)blockIdx.x*256 + threadIdx.x;   // over 11*S
    const float* W; bf16 *H, *L; long j;
    if      (i < S)       { W=Wq;  H=WqH;  L=WqL;  j=i; }
    else if (i < 2L*S)    { W=Wv;  H=WvH;  L=WvL;  j=i-S; }
    else if (i < 3L*S)    { W=Wo;  H=WoH;  L=WoL;  j=i-2L*S; }
    else if (i < 7L*S)    { W=Wfc; H=WfcH; L=WfcL; j=i-3L*S; }
    else                  { W=Wpr; H=WprH; L=WprL; j=i-7L*S; }
    float x = W[j];
    bf16 h, l; split2(x, h, l);
    H[j] = h; L[j] = l;
}

__global__ void frob1(const float* __restrict__ W1, const float* __restrict__ W2,
                      float* __restrict__ part)
{
    const int row = blockIdx.x, mat = blockIdx.y, tid = threadIdx.x;
    const float* W = mat ? W2 : W1;
    float4 f = ((const float4*)(W + (long)row*Cv))[tid];
    float q = f.x*f.x+f.y*f.y+f.z*f.z+f.w*f.w;
    __shared__ float shq[4];
#pragma unroll
    for (int off=16; off>0; off>>=1) q += __shfl_down_sync(0xffffffffu, q, off);
    if ((tid&31)==0) shq[tid>>5]=q;
    __syncthreads();
    if (tid==0) part[mat*Cv + row] = shq[0]+shq[1]+shq[2]+shq[3];
}

__global__ void frob2(const float* __restrict__ part, float* __restrict__ rn)
{
    const int mat = blockIdx.x, tid = threadIdx.x;
    __shared__ float sh[256];
    sh[tid] = part[mat*Cv + tid] + part[mat*Cv + tid + 256];
    __syncthreads();
    for (int off=128; off>0; off>>=1) {
        if (tid<off) sh[tid] += sh[tid+off];
        __syncthreads();
    }
    if (tid==0) rn[mat] = rsqrtf(sh[0]);
}

// X = W * rn, split to H/L, plus transposed copies. grid (16,16,2), block (32,8).
__global__ void split_tr_init(const float* __restrict__ W1, const float* __restrict__ W2,
                              const float* __restrict__ rn,
                              bf16* XH, bf16* XL, bf16* XtH, bf16* XtL)
{
    __shared__ float t[32][33];
    const int mat = blockIdx.z;
    const float* W = mat ? W2 : W1;
    const float s = rn[mat];
    const int r0 = blockIdx.y*32, c0 = blockIdx.x*32;
    const int tx = threadIdx.x, ty = threadIdx.y;
    const long mo = (long)mat*Sm;
#pragma unroll
    for (int i = 0; i < 4; i++) {
        int rr = ty + i*8;
        t[rr][tx] = W[(long)(r0+rr)*Cv + c0+tx] * s;
    }
    __syncthreads();
#pragma unroll
    for (int i = 0; i < 4; i++) {
        int rr = ty + i*8;
        bf16 h, l;
        split2(t[rr][tx], h, l);
        XH[mo + (long)(r0+rr)*Cv + c0+tx] = h;
        XL[mo + (long)(r0+rr)*Cv + c0+tx] = l;
        split2(t[tx][rr], h, l);
        XtH[mo + (long)(c0+rr)*Cv + r0+tx] = h;
        XtL[mo + (long)(c0+rr)*Cv + r0+tx] = l;
    }
}

// Pc[n, 0:512] = P1[n,:], Pc[n, 512:1024] = P2[n,:]
__global__ void packP(const bf16* __restrict__ XH, const bf16* __restrict__ XL,
                      bf16* __restrict__ PcH, bf16* __restrict__ PcL)
{
    int idx = blockIdx.x*256 + threadIdx.x;     // over 512*1024
    int n = idx >> 10, k = idx & 1023;
    long src = (k < 512) ? ((long)n*Cv + k) : (Sm + (long)n*Cv + (k-512));
    PcH[idx] = XH[src];
    PcL[idx] = XL[src];
}

// ---------------- host ----------------
static inline GA mkga(const bf16* Ah, const bf16* Al, const bf16* Bh, const bf16* Bl,
                      int M, int N, int K, int lda, int ldb, long zA = 0, long zB = 0)
{
    GA g; g.Ah=Ah; g.Al=Al; g.Ah2=Ah; g.Al2=Al; g.Bh=Bh; g.Bl=Bl;
    g.M=M; g.N=N; g.K=K; g.K1=K; g.lda=lda; g.ldb=ldb; g.mskip=0; g.zA=zA; g.zB=zB;
    return g;
}
static inline TEpi te()
{
    TEpi e; e.alpha=1.f; e.beta=1.f; e.diag=0.f; e.add=0; e.zAdd=0;
    e.gelu=0; e.outF=0; e.outH=0; e.outL=0; e.zOut=0; e.outTH=0; e.outTL=0;
    return e;
}

#define SM128 (3*4*128*64)                   // 98304: 128x128 tiles, 3 stages
#define SMP   (5*(2*32*64 + 2*64*64))        // 61440: polar 32x64 tiles, 5 stages

extern "C" void kernel_launch(void* const* d_in, const int* in_sizes, int n_in,
                              void* d_out, int out_size)
{
    const float* x   = (const float*)d_in[0];
    const float* ln1 = (const float*)d_in[1];
    const float* Wq  = (const float*)d_in[2];
    const float* Wv  = (const float*)d_in[3];
    const float* Wo  = (const float*)d_in[4];
    // d_in[5] = identity : mathematically unused (rows computed from it are discarded)
    const float* Wp1 = (const float*)d_in[6];
    const float* Wp2 = (const float*)d_in[7];
    const float* ln2 = (const float*)d_in[8];
    const float* Wfc = (const float*)d_in[9];
    const float* Wpr = (const float*)d_in[10];
    float* out = (float*)d_out;

    cudaFuncSetAttribute(mma_gemm<128,128,2,2,3>, cudaFuncAttributeMaxDynamicSharedMemorySize, SM128);
    cudaFuncSetAttribute(mma_gemm<32,64,2,3,5>,   cudaFuncAttributeMaxDynamicSharedMemorySize, SMP);

    // streams: sP = polar chain, sM = main prep; both forked off the capture
    // origin stream and joined before the scan.
    static cudaStream_t sP = 0, sM = 0;
    static cudaEvent_t evF = 0, evJ = 0, evM = 0;
    if (!sP) {
        cudaStreamCreateWithFlags(&sP, cudaStreamNonBlocking);
        cudaStreamCreateWithFlags(&sM, cudaStreamNonBlocking);
        cudaEventCreateWithFlags(&evF, cudaEventDisableTiming);
        cudaEventCreateWithFlags(&evJ, cudaEventDisableTiming);
        cudaEventCreateWithFlags(&evM, cudaEventDisableTiming);
    }

    bf16 *qH,*qL,*vH,*vL,*hH,*hL,*fcH,*fcL;
    bf16 *WqH,*WqL,*WvH,*WvL,*WoH,*WoL,*WfcH,*WfcL,*WprH,*WprL;
    bf16 *XaH,*XaL,*XbH,*XbL,*XtH,*XtL,*YH,*YL,*MH,*ML,*PcH,*PcL;
    float *z,*YF,*part,*rn;
    cudaGetSymbolAddress((void**)&qH, g_qH);   cudaGetSymbolAddress((void**)&qL, g_qL);
    cudaGetSymbolAddress((void**)&vH, g_vH);   cudaGetSymbolAddress((void**)&vL, g_vL);
    cudaGetSymbolAddress((void**)&z,  g_z);
    cudaGetSymbolAddress((void**)&hH, g_hH);   cudaGetSymbolAddress((void**)&hL, g_hL);
    cudaGetSymbolAddress((void**)&fcH, g_fcH); cudaGetSymbolAddress((void**)&fcL, g_fcL);
    cudaGetSymbolAddress((void**)&WqH, g_WqH); cudaGetSymbolAddress((void**)&WqL, g_WqL);
    cudaGetSymbolAddress((void**)&WvH, g_WvH); cudaGetSymbolAddress((void**)&WvL, g_WvL);
    cudaGetSymbolAddress((void**)&WoH, g_WoH); cudaGetSymbolAddress((void**)&WoL, g_WoL);
    cudaGetSymbolAddress((void**)&WfcH,g_WfcH); cudaGetSymbolAddress((void**)&WfcL,g_WfcL);
    cudaGetSymbolAddress((void**)&WprH,g_WprH); cudaGetSymbolAddress((void**)&WprL,g_WprL);
    cudaGetSymbolAddress((void**)&XaH, g_XaH); cudaGetSymbolAddress((void**)&XaL, g_XaL);
    cudaGetSymbolAddress((void**)&XbH, g_XbH); cudaGetSymbolAddress((void**)&XbL, g_XbL);
    cudaGetSymbolAddress((void**)&XtH, g_XtH); cudaGetSymbolAddress((void**)&XtL, g_XtL);
    cudaGetSymbolAddress((void**)&YH,  g_YH);  cudaGetSymbolAddress((void**)&YL,  g_YL);
    cudaGetSymbolAddress((void**)&MH,  g_MH);  cudaGetSymbolAddress((void**)&ML,  g_ML);
    cudaGetSymbolAddress((void**)&PcH, g_PcH); cudaGetSymbolAddress((void**)&PcL, g_PcL);
    cudaGetSymbolAddress((void**)&YF,  g_YF);
    cudaGetSymbolAddress((void**)&part,g_part);
    cudaGetSymbolAddress((void**)&rn,  g_rn);

    // ---- fork ----
    cudaEventRecord(evF, 0);
    cudaStreamWaitEvent(sP, evF, 0);
    cudaStreamWaitEvent(sM, evF, 0);

    {   // polar factors via Muon-quintic + Newton-Schulz on tensor cores (stream sP)
        frob1<<<dim3(Cv,2),128,0,sP>>>(Wp1, Wp2, part);
        frob2<<<2,256,0,sP>>>(part, rn);
        split_tr_init<<<dim3(16,16,2),dim3(32,8),0,sP>>>(Wp1, Wp2, rn, XaH, XaL, XtH, XtL);

        const dim3 gp(Cv/64, Cv/32, 2);     // (8,16,2) = 256 CTAs, 32x64 tiles
        for (int it = 0; it < 9; ++it) {
            // Y = Xt @ Xt^T  (= X^T X, symmetric)
            GA g1 = mkga(XtH, XtL, XtH, XtL, Cv, Cv, Cv, Cv, Cv, Sm, Sm);
            TEpi e1 = te(); e1.outF = YF; e1.outH = YH; e1.outL = YL; e1.zOut = Sm;
            mma_gemm<32,64,2,3,5><<<gp,256,SMP,sP>>>(g1, e1);
            // M = 2.0315*Y@Y^T - 4.7750*Y + 3.4445*I  (symmetric)
            GA g2 = mkga(YH, YL, YH, YL, Cv, Cv, Cv, Cv, Cv, Sm, Sm);
            TEpi e2 = te(); e2.alpha = 2.0315f; e2.add = YF; e2.zAdd = Sm;
            e2.beta = -4.7750f; e2.diag = 3.4445f; e2.outH = MH; e2.outL = ML; e2.zOut = Sm;
            mma_gemm<32,64,2,3,5><<<gp,256,SMP,sP>>>(g2, e2);
            // X' = X @ M^T (= X M, M symmetric); epilogue also emits Xt'
            GA g3 = mkga(XaH, XaL, MH, ML, Cv, Cv, Cv, Cv, Cv, Sm, Sm);
            TEpi e3 = te(); e3.outH = XbH; e3.outL = XbL; e3.zOut = Sm;
            e3.outTH = XtH; e3.outTL = XtL;
            mma_gemm<32,64,2,3,5><<<gp,256,SMP,sP>>>(g3, e3);
            bf16* t;
            t = XaH; XaH = XbH; XbH = t;
            t = XaL; XaL = XbL; XbL = t;
        }
        for (int it = 0; it < 4; ++it) {
            // G = -0.5*Xt@Xt^T + 1.5I  (symmetric)
            GA g1 = mkga(XtH, XtL, XtH, XtL, Cv, Cv, Cv, Cv, Cv, Sm, Sm);
            TEpi e1 = te(); e1.alpha = -0.5f; e1.diag = 1.5f;
            e1.outH = MH; e1.outL = ML; e1.zOut = Sm;
            mma_gemm<32,64,2,3,5><<<gp,256,SMP,sP>>>(g1, e1);
            // X' = X @ G^T; epilogue also emits Xt'
            GA g2 = mkga(XaH, XaL, MH, ML, Cv, Cv, Cv, Cv, Cv, Sm, Sm);
            TEpi e2 = te(); e2.outH = XbH; e2.outL = XbL; e2.zOut = Sm;
            e2.outTH = XtH; e2.outTL = XtL;
            mma_gemm<32,64,2,3,5><<<gp,256,SMP,sP>>>(g2, e2);
            bf16* t;
            t = XaH; XaH = XbH; XbH = t;
            t = XaL; XaL = XbL; XbL = t;
        }
        packP<<<(Cv*2*Cv)/256,256,0,sP>>>(XaH, XaL, PcH, PcL);
        cudaEventRecord(evJ, sP);
    }

    {   // main prep: weight splits + ln + q/v GEMMs (stream sM, concurrent w/ polar)
        wsplit5<<<(11*Cv*Cv)/256,256,0,sM>>>(Wq, Wv, Wo, Wfc, Wpr,
            WqH, WqL, WvH, WvL, WoH, WoL, WfcH, WfcL, WprH, WprL);
        ln_kernel<<<Rv,128,0,sM>>>(x, ln1, hH, hL);
        GA gq = mkga(hH, hL, WqH, WqL, Rv, Cv, Cv, Cv, Cv);
        TEpi eq = te(); eq.outH = qH + GUARDE; eq.outL = qL + GUARDE;
        mma_gemm<128,128,2,2,3><<<dim3(Cv/128, Rv/128), 256, SM128, sM>>>(gq, eq);
        GA gv = mkga(hH, hL, WvH, WvL, Rv, Cv, Cv, Cv, Cv);
        TEpi ev = te(); ev.outH = vH; ev.outL = vL;
        mma_gemm<128,128,2,2,3><<<dim3(Cv/128, Rv/128), 256, SM128, sM>>>(gv, ev);
        cudaEventRecord(evM, sM);
    }

    // ---- join: scan needs Pc (sP) and q (sM) ----
    cudaStreamWaitEvent(0, evJ, 0);
    cudaStreamWaitEvent(0, evM, 0);

    for (int d = 1; d < Tv; d <<= 1) {
        const int mskip = d & ~127;          // whole 128-row tiles with t<d skipped
        // z = qshift @ P1^T + q @ P2^T : single GEMM, K=1024
        // chunks k<512 read q[t-d] (guard zeros / stale rows, discarded), k>=512 read q[t]
        GA gs = mkga(qH + GUARDE, qL + GUARDE, PcH, PcL, Rv, Cv, 2*Cv, Cv, 2*Cv);
        gs.Ah = qH + GUARDE - (long)d*Cv;
        gs.Al = qL + GUARDE - (long)d*Cv;
        gs.K1 = Cv;
        gs.mskip = mskip;
        gs.zA = (long)Tv*Cv;                  // batch stride (rows)
        TEpi es = te(); es.outF = z; es.zOut = (long)Tv*Cv;
        mma_gemm<128,128,2,2,3><<<dim3(Cv/128, (Tv-mskip)/128, Bv), 256, SM128>>>(gs, es);
        pscan_combine<<<dim3((Tv-mskip)/4, Bv),512>>>(z, qH + GUARDE, qL + GUARDE, d, mskip);
    }

    // x1 = x + (q*v) @ Wo^T   (into d_out)
    mul_split<<<(Rv*Cv/4)/256,256>>>(qH + GUARDE, qL + GUARDE, vH, vL, hH, hL);
    {
        GA go = mkga(hH, hL, WoH, WoL, Rv, Cv, Cv, Cv, Cv);
        TEpi er = te(); er.add = x; er.outF = out;
        mma_gemm<128,128,2,2,3><<<dim3(Cv/128, Rv/128), 256, SM128>>>(go, er);
    }

    // ---- MLP branch ----
    ln_kernel<<<Rv,128>>>(out, ln2, hH, hL);
    {
        GA gf = mkga(hH, hL, WfcH, WfcL, Rv, Fv, Cv, Cv, Cv);
        TEpi eg = te(); eg.gelu = 1; eg.outH = fcH; eg.outL = fcL;
        mma_gemm<128,128,2,2,3><<<dim3(Fv/128, Rv/128), 256, SM128>>>(gf, eg);
        GA gr = mkga(fcH, fcL, WprH, WprL, Rv, Cv, Fv, Fv, Fv);
        TEpi er2 = te(); er2.add = out; er2.outF = out;
        mma_gemm<128,128,2,2,3><<<dim3(Cv/128, Rv/128), 256, SM128>>>(gr, er2);
    }
}

// round 15
// speedup vs baseline: 1.1869x; 1.0172x over previous
#include <cuda_runtime.h>
#include <cuda_bf16.h>
#include <math.h>
#include <stdint.h>

#define Bv 4
#define Tv 4096
#define Cv 512
#define Rv (Bv*Tv)            // 16384 rows
#define Fv (4*Cv)             // 2048
#define GUARDE (2048*Cv)      // guard rows (zero-init) for shifted scan operand
#define Sm ((long)Cv*Cv)

typedef __nv_bfloat16 bf16;

// ---------------- static device scratch (zero-initialized) ----------------
__device__ bf16 g_qH[GUARDE + Rv*Cv];
__device__ bf16 g_qL[GUARDE + Rv*Cv];
__device__ bf16 g_vH[Rv*Cv], g_vL[Rv*Cv];
__device__ float g_z[Rv*Cv];
__device__ bf16 g_hH[Rv*Cv], g_hL[Rv*Cv];
__device__ bf16 g_fcH[Rv*Fv], g_fcL[Rv*Fv];
// weight splits
__device__ bf16 g_WqH[Cv*Cv], g_WqL[Cv*Cv];
__device__ bf16 g_WvH[Cv*Cv], g_WvL[Cv*Cv];
__device__ bf16 g_WoH[Cv*Cv], g_WoL[Cv*Cv];
__device__ bf16 g_WfcH[Fv*Cv], g_WfcL[Fv*Cv];
__device__ bf16 g_WprH[Cv*Fv], g_WprL[Cv*Fv];
// polar scratch (x2 matrices, batched)
__device__ bf16 g_XaH[2*Cv*Cv], g_XaL[2*Cv*Cv];
__device__ bf16 g_XbH[2*Cv*Cv], g_XbL[2*Cv*Cv];
__device__ bf16 g_XtH[2*Cv*Cv], g_XtL[2*Cv*Cv];
__device__ bf16 g_YH [2*Cv*Cv], g_YL [2*Cv*Cv];
__device__ bf16 g_MH [2*Cv*Cv], g_ML [2*Cv*Cv];
__device__ float g_YF[2*Cv*Cv];
__device__ bf16 g_PcH[Cv*2*Cv], g_PcL[Cv*2*Cv];   // [P1||P2] along K (512 x 1024)
__device__ float g_part[2*Cv];
__device__ float g_rn[2];
// software grid barrier state (zero-init; count returns to 0 after each barrier)
__device__ int g_barC;
__device__ volatile int g_barGen;

// ================= helpers =================
__device__ __forceinline__ uint32_t smem_to_u32(const void* p) {
    uint32_t a;
    asm("{ .reg .u64 t; cvta.to.shared.u64 t, %1; cvt.u32.u64 %0, t; }" : "=r"(a) : "l"(p));
    return a;
}
__device__ __forceinline__ void split2(float x, bf16& h, bf16& l) {
    h = __float2bfloat16(x);
    l = __float2bfloat16(x - __bfloat162float(h));
}
__device__ __forceinline__ uint32_t pk2(bf16 a, bf16 b) {
    __nv_bfloat162 t; t.x = a; t.y = b;
    return *(uint32_t*)&t;
}
__device__ __forceinline__ void up2(uint32_t u, float& a, float& b) {
    __nv_bfloat162 t = *(__nv_bfloat162*)&u;
    a = __bfloat162float(t.x); b = __bfloat162float(t.y);
}
__device__ __forceinline__ void ldsm4(uint32_t (&r)[4], uint32_t addr) {
    asm volatile("ldmatrix.sync.aligned.m8n8.x4.shared.b16 {%0,%1,%2,%3}, [%4];"
        : "=r"(r[0]), "=r"(r[1]), "=r"(r[2]), "=r"(r[3]) : "r"(addr));
}
__device__ __forceinline__ void mma16816(float (&d)[4], const uint32_t (&a)[4],
                                         uint32_t b0, uint32_t b1) {
    asm volatile("mma.sync.aligned.m16n8k16.row.col.f32.bf16.bf16.f32 "
        "{%0,%1,%2,%3}, {%4,%5,%6,%7}, {%8,%9}, {%0,%1,%2,%3};"
        : "+f"(d[0]), "+f"(d[1]), "+f"(d[2]), "+f"(d[3])
        : "r"(a[0]), "r"(a[1]), "r"(a[2]), "r"(a[3]), "r"(b0), "r"(b1));
}
__device__ __forceinline__ void cp_async16(uint32_t so, const void* gp) {
    asm volatile("cp.async.cg.shared.global [%0], [%1], 16;" :: "r"(so), "l"(gp) : "memory");
}
#define CP_COMMIT() asm volatile("cp.async.commit_group;" ::: "memory")
#define CP_WAIT(n)  asm volatile("cp.async.wait_group %0;" :: "n"(n) : "memory")

// all-256-CTA grid barrier (all CTAs co-resident: 256 <= 148 SMs x 2 occupancy)
__device__ __forceinline__ void gridbar() {
    __syncthreads();
    if (threadIdx.x == 0) {
        int gen = g_barGen;
        __threadfence();
        if (atomicAdd(&g_barC, 1) == 255) {
            g_barC = 0;
            __threadfence();
            g_barGen = gen + 1;
        } else {
            while (g_barGen == gen) { }
        }
    }
    __syncthreads();
}

// ================= mma.sync split-bf16 GEMM: C = alpha*A@B^T (+beta*add +diag*I) =====
// (big-GEMM path; 128x128 @ OCC=2 / 3-stage is the measured optimum)
struct GA {
    const bf16 *Ah, *Al, *Ah2, *Al2, *Bh, *Bl;
    int M, N, K, K1, lda, ldb, mskip;
    long zA, zB;
};
struct TEpi {
    float alpha, beta, diag;
    const float* add; long zAdd;
    int gelu;
    float* outF; bf16 *outH, *outL; long zOut;
    bf16 *outTH, *outTL;
};

template<int BM, int BN, int WR, int OCC, int NSTG>
__global__ __launch_bounds__(256, OCC)
void mma_gemm(GA g, TEpi e)
{
    constexpr int WC = 8/WR;
    constexpr int MF = BM/(16*WR);
    constexpr int NF = (BN/WC)/8;
    constexpr int NB = NF/2;
    static_assert(MF >= 1 && NB >= 1, "tile too small");
    constexpr int ASZA = BM*64;
    constexpr int ASZB = BN*64;
    constexpr int BUF = 2*ASZA + 2*ASZB;
    extern __shared__ char smem[];
    const uint32_t sb = smem_to_u32(smem);
    const int tid  = threadIdx.x;
    const int lane = tid & 31;
    const int wid  = tid >> 5;
    const int wm   = wid % WR;
    const int wn   = wid / WR;
    const int m0 = g.mskip + blockIdx.y * BM;
    const int n0 = blockIdx.x * BN;
    const int bz = blockIdx.z;
    const int NC = g.K / 32;

    const bf16 *Ah = g.Ah + bz*g.zA,  *Al = g.Al + bz*g.zA;
    const bf16 *Ah2 = g.Ah2 + bz*g.zA, *Al2 = g.Al2 + bz*g.zA;
    const bf16 *Bh = g.Bh + bz*g.zB,  *Bl = g.Bl + bz*g.zB;

    int aOff[2][MF], bOff[2][NB];
    {
        const int aKb = (lane >> 4) * 16;
#pragma unroll
        for (int mf = 0; mf < MF; mf++) {
            int r = wm * (BM/WR) + mf * 16 + (lane & 15);
            int base = (r >> 1) * 128, po = (r & 1) * 64, xm = ((r >> 1) & 7) << 4;
#pragma unroll
            for (int ks = 0; ks < 2; ks++)
                aOff[ks][mf] = base + ((po + ks * 32 + aKb) ^ xm);
        }
        const int bKb = ((lane >> 3) & 1) * 16;
#pragma unroll
        for (int nb = 0; nb < NB; nb++) {
            int r = wn * (BN/WC) + nb * 16 + ((lane >> 4) << 3) + (lane & 7);
            int base = (r >> 1) * 128, po = (r & 1) * 64, xm = ((r >> 1) & 7) << 4;
#pragma unroll
            for (int ks = 0; ks < 2; ks++)
                bOff[ks][nb] = base + ((po + ks * 32 + bKb) ^ xm);
        }
    }

    float acc[MF][NF][4];
#pragma unroll
    for (int i = 0; i < MF; i++)
#pragma unroll
        for (int j = 0; j < NF; j++)
#pragma unroll
            for (int t = 0; t < 4; t++) acc[i][j][t] = 0.f;

    auto loadChunk = [&](int c) {
        const long cofs = (long)c * 32;
        const int st = c % NSTG;
        const bf16* AHc = Ah; const bf16* ALc = Al;
        long acol = cofs;
        if (cofs >= g.K1) { AHc = Ah2; ALc = Al2; acol = cofs - g.K1; }
        constexpr int TVA = BM * 4;
        constexpr int TVB = BN * 4;
        constexpr int NVEC = 2*TVA + 2*TVB;
#pragma unroll
        for (int t = 0; t < NVEC/256; t++) {
            int u = tid + t * 256;
            const bf16* base;
            int row, seg, sofs;
            if (u < TVA)            { base = AHc; row = u >> 2;          seg = u & 3;        sofs = 0;           }
            else if (u < 2*TVA)     { base = ALc; row = (u-TVA) >> 2;    seg = (u-TVA) & 3;  sofs = ASZA;        }
            else if (u < 2*TVA+TVB) { base = Bh;  row = (u-2*TVA) >> 2;  seg = (u-2*TVA) & 3; sofs = 2*ASZA;     }
            else                    { base = Bl;  row = (u-2*TVA-TVB) >> 2; seg = (u-2*TVA-TVB) & 3; sofs = 2*ASZA+ASZB; }
            const bf16* gp;
            if (sofs < 2*ASZA) gp = base + (long)(m0 + row) * g.lda + acol;
            else               gp = base + (long)(n0 + row) * g.ldb + cofs;
            gp += seg * 8;
            int j = row >> 1, p = row & 1;
            uint32_t so = sb + st * BUF + sofs + j * 128
                        + ((p * 64 + seg * 16) ^ ((j & 7) << 4));
            cp_async16(so, gp);
        }
        CP_COMMIT();
    };

    for (int i = 0; i < NSTG - 1 && i < NC; i++) loadChunk(i);

    for (int c = 0; c < NC; c++) {
        int rem = NC - 1 - c;
        if (rem > NSTG - 2) rem = NSTG - 2;
        if (NSTG >= 5 && rem >= 3)      CP_WAIT(3);
        else if (NSTG >= 4 && rem >= 2) CP_WAIT(2);
        else if (rem >= 1)              CP_WAIT(1);
        else                            CP_WAIT(0);
        __syncthreads();
        if (c + NSTG - 1 < NC) loadChunk(c + NSTG - 1);

        const uint32_t bufB = sb + (c % NSTG) * BUF;
#pragma unroll
        for (int ks = 0; ks < 2; ks++) {
            uint32_t afH[MF][4], bfH[NB][4];
#pragma unroll
            for (int mf = 0; mf < MF; mf++)
                ldsm4(afH[mf], bufB + aOff[ks][mf]);
#pragma unroll
            for (int nb = 0; nb < NB; nb++)
                ldsm4(bfH[nb], bufB + 2*ASZA + bOff[ks][nb]);
#pragma unroll
            for (int mf = 0; mf < MF; mf++)
#pragma unroll
                for (int nf = 0; nf < NF; nf++)
                    mma16816(acc[mf][nf], afH[mf], bfH[nf>>1][(nf&1)*2], bfH[nf>>1][(nf&1)*2+1]);
            {
                uint32_t afL[MF][4];
#pragma unroll
                for (int mf = 0; mf < MF; mf++)
                    ldsm4(afL[mf], bufB + ASZA + aOff[ks][mf]);
#pragma unroll
                for (int mf = 0; mf < MF; mf++)
#pragma unroll
                    for (int nf = 0; nf < NF; nf++)
                        mma16816(acc[mf][nf], afL[mf], bfH[nf>>1][(nf&1)*2], bfH[nf>>1][(nf&1)*2+1]);
            }
            {
                uint32_t bfL[NB][4];
#pragma unroll
                for (int nb = 0; nb < NB; nb++)
                    ldsm4(bfL[nb], bufB + 2*ASZA + ASZB + bOff[ks][nb]);
#pragma unroll
                for (int mf = 0; mf < MF; mf++)
#pragma unroll
                    for (int nf = 0; nf < NF; nf++)
                        mma16816(acc[mf][nf], afH[mf], bfL[nf>>1][(nf&1)*2], bfL[nf>>1][(nf&1)*2+1]);
            }
        }
    }
    __syncthreads();

    // ---- epilogue ----
    float* outF = e.outF ? e.outF + bz*e.zOut : (float*)0;
    bf16*  outH = e.outH ? e.outH + bz*e.zOut : (bf16*)0;
    bf16*  outL = e.outL ? e.outL + bz*e.zOut : (bf16*)0;
    const float* add = e.add ? e.add + bz*e.zAdd : (const float*)0;
    const int rl = lane >> 2;
    const int cl = (lane & 3) * 2;
#pragma unroll
    for (int mf = 0; mf < MF; mf++) {
#pragma unroll
        for (int nf = 0; nf < NF; nf++) {
            int lc = wn * (BN/WC) + nf * 8 + cl;
            int c0 = n0 + lc;
#pragma unroll
            for (int half = 0; half < 2; half++) {
                int lr = wm * (BM/WR) + mf * 16 + rl + half * 8;
                int row = m0 + lr;
                long ofs = (long)row * g.N + c0;
                float f0 = e.alpha * acc[mf][nf][half*2];
                float f1 = e.alpha * acc[mf][nf][half*2 + 1];
                if (add) {
                    float2 ra = *(const float2*)(add + ofs);
                    f0 += e.beta * ra.x; f1 += e.beta * ra.y;
                }
                if (e.diag != 0.f) {
                    if (row == c0)     f0 += e.diag;
                    if (row == c0 + 1) f1 += e.diag;
                }
                if (e.gelu) {
                    f0 = 0.5f * f0 * (1.f + erff(f0 * 0.70710678118654752f));
                    f1 = 0.5f * f1 * (1.f + erff(f1 * 0.70710678118654752f));
                }
                if (outF)
                    *(float2*)(outF + ofs) = make_float2(f0, f1);
                if (outH) {
                    bf16 h0, h1, l0, l1;
                    split2(f0, h0, l0);
                    split2(f1, h1, l1);
                    *(uint32_t*)(outH + ofs) = pk2(h0, h1);
                    *(uint32_t*)(outL + ofs) = pk2(l0, l1);
                }
            }
        }
    }
}

// ================= persistent polar chain (35 fused GEMM phases) =================
struct PArg {
    const bf16 *Ah, *Al, *Bh, *Bl;   // operands (pre-offset by mat), pitch Cv, [*,K=512]
    float alpha, beta, diag;
    const float* add;                // pitch Cv
    float* outF;                     // pitch Cv
    bf16 *outH, *outL; int ldo;      // pitch ldo
    bf16 *outTH, *outTL;             // transposed out, pitch Cv
};

// one 32x64 tile, K=512, 3-stage cp.async; 8 warps (2x4)
__device__ void pgemm(char* smem, int m0, int n0, const PArg& p)
{
    constexpr int ASZA = 2048, ASZB = 4096, BUF = 2*ASZA + 2*ASZB;  // 12288
    const uint32_t sb = smem_to_u32(smem);
    const int tid = threadIdx.x, lane = tid & 31, wid = tid >> 5;
    const int wm = wid & 1, wn = wid >> 1;
    const int NC = 16;

    int aOff[2], bOff[2];
    {
        const int aKb = (lane >> 4) * 16;
        int r = wm*16 + (lane & 15);
        int base = (r>>1)*128, po = (r&1)*64, xm = ((r>>1)&7)<<4;
        aOff[0] = base + ((po + aKb) ^ xm);
        aOff[1] = base + ((po + 32 + aKb) ^ xm);
        const int bKb = ((lane >> 3) & 1) * 16;
        r = wn*16 + ((lane >> 4) << 3) + (lane & 7);
        base = (r>>1)*128; po = (r&1)*64; xm = ((r>>1)&7)<<4;
        bOff[0] = base + ((po + bKb) ^ xm);
        bOff[1] = base + ((po + 32 + bKb) ^ xm);
    }

    float acc[2][4];
#pragma unroll
    for (int j = 0; j < 2; j++)
#pragma unroll
        for (int t = 0; t < 4; t++) acc[j][t] = 0.f;

    auto loadChunk = [&](int c) {
        const long cofs = (long)c * 32;
        const int st = c % 3;
#pragma unroll
        for (int t = 0; t < 3; t++) {
            int u = tid + t * 256;
            const bf16* base; int row, seg, sofs;
            if (u < 128)      { base = p.Ah; row = u >> 2;        seg = u & 3;        sofs = 0; }
            else if (u < 256) { base = p.Al; row = (u-128) >> 2;  seg = (u-128) & 3;  sofs = ASZA; }
            else if (u < 512) { base = p.Bh; row = (u-256) >> 2;  seg = (u-256) & 3;  sofs = 2*ASZA; }
            else              { base = p.Bl; row = (u-512) >> 2;  seg = (u-512) & 3;  sofs = 2*ASZA+ASZB; }
            const bf16* gp = (sofs < 2*ASZA) ? base + (long)(m0 + row) * Cv + cofs
                                             : base + (long)(n0 + row) * Cv + cofs;
            gp += seg * 8;
            int j = row >> 1, pp = row & 1;
            uint32_t so = sb + st * BUF + sofs + j * 128
                        + ((pp * 64 + seg * 16) ^ ((j & 7) << 4));
            cp_async16(so, gp);
        }
        CP_COMMIT();
    };

    loadChunk(0);
    loadChunk(1);
    for (int c = 0; c < NC; c++) {
        if (c + 1 < NC) CP_WAIT(1); else CP_WAIT(0);
        __syncthreads();
        if (c + 2 < NC) loadChunk(c + 2);
        const uint32_t bufB = sb + (c % 3) * BUF;
#pragma unroll
        for (int ks = 0; ks < 2; ks++) {
            uint32_t afH[4], bfH[4];
            ldsm4(afH, bufB + aOff[ks]);
            ldsm4(bfH, bufB + 2*ASZA + bOff[ks]);
            mma16816(acc[0], afH, bfH[0], bfH[1]);
            mma16816(acc[1], afH, bfH[2], bfH[3]);
            uint32_t afL[4];
            ldsm4(afL, bufB + ASZA + aOff[ks]);
            mma16816(acc[0], afL, bfH[0], bfH[1]);
            mma16816(acc[1], afL, bfH[2], bfH[3]);
            uint32_t bfL[4];
            ldsm4(bfL, bufB + 2*ASZA + ASZB + bOff[ks]);
            mma16816(acc[0], afH, bfL[0], bfL[1]);
            mma16816(acc[1], afH, bfL[2], bfL[3]);
        }
    }
    __syncthreads();

    // epilogue (smem reused for transpose staging)
    bf16* sH = (bf16*)smem;
    bf16* sL = sH + 32*65;
    const int rl = lane >> 2, cl = (lane & 3) * 2;
#pragma unroll
    for (int nf = 0; nf < 2; nf++) {
        int lc = wn*16 + nf*8 + cl;
        int c0 = n0 + lc;
#pragma unroll
        for (int half = 0; half < 2; half++) {
            int lr = wm*16 + rl + half*8;
            int row = m0 + lr;
            float f0 = p.alpha * acc[nf][half*2];
            float f1 = p.alpha * acc[nf][half*2 + 1];
            if (p.add) {
                float2 ra = *(const float2*)(p.add + (long)row*Cv + c0);
                f0 += p.beta * ra.x; f1 += p.beta * ra.y;
            }
            if (p.diag != 0.f) {
                if (row == c0)     f0 += p.diag;
                if (row == c0 + 1) f1 += p.diag;
            }
            if (p.outF)
                *(float2*)(p.outF + (long)row*Cv + c0) = make_float2(f0, f1);
            bf16 h0, h1, l0, l1;
            split2(f0, h0, l0);
            split2(f1, h1, l1);
            if (p.outH) {
                long ofs = (long)row * p.ldo + c0;
                *(uint32_t*)(p.outH + ofs) = pk2(h0, h1);
                *(uint32_t*)(p.outL + ofs) = pk2(l0, l1);
            }
            if (p.outTH) {
                sH[lr*65 + lc] = h0; sH[lr*65 + lc + 1] = h1;
                sL[lr*65 + lc] = l0; sL[lr*65 + lc + 1] = l1;
            }
        }
    }
    if (p.outTH) {
        __syncthreads();
#pragma unroll
        for (int it = 0; it < 8; it++) {
            int idx = tid + it * 256;
            int j = idx >> 5;   // col 0..63
            int i = idx & 31;   // row 0..31
            long o = (long)(n0 + j) * Cv + m0 + i;
            p.outTH[o] = sH[i*65 + j];
            p.outTL[o] = sL[i*65 + j];
        }
    }
}

__global__ __launch_bounds__(256, 2)
void polar_chain(bf16* XaH0, bf16* XaL0, bf16* XbH0, bf16* XbL0,
                 bf16* XtH, bf16* XtL, bf16* YH, bf16* YL,
                 bf16* MH, bf16* ML, float* YF, bf16* PcH, bf16* PcL)
{
    __shared__ char smem[36864];
    const int cid = blockIdx.x;          // 256 CTAs: 2 mats x (16 x 8) tiles
    const int mat = cid >> 7;
    const int m0 = ((cid >> 3) & 15) * 32;
    const int n0 = (cid & 7) * 64;
    const long mo = (long)mat * Sm;
    bf16 *aH = XaH0 + mo, *aL = XaL0 + mo, *bH = XbH0 + mo, *bL = XbL0 + mo;
    bf16 *tH = XtH + mo, *tL = XtL + mo;
    bf16 *yH = YH + mo, *yL = YL + mo, *mH = MH + mo, *mL = ML + mo;
    float* yF = YF + mo;

    for (int it = 0; it < 9; it++) {
        // Y = Xt @ Xt^T (= X^T X)
        { PArg p{tH,tL,tH,tL, 1.f,0.f,0.f, 0, yF, yH,yL,Cv, 0,0}; pgemm(smem,m0,n0,p); }
        gridbar();
        // M = 2.0315*Y@Y^T - 4.7750*Y + 3.4445*I
        { PArg p{yH,yL,yH,yL, 2.0315f,-4.7750f,3.4445f, yF, 0, mH,mL,Cv, 0,0}; pgemm(smem,m0,n0,p); }
        gridbar();
        // X' = X @ M^T; also emit Xt'
        { PArg p{aH,aL,mH,mL, 1.f,0.f,0.f, 0, 0, bH,bL,Cv, tH,tL}; pgemm(smem,m0,n0,p); }
        gridbar();
        bf16* t;
        t = aH; aH = bH; bH = t;
        t = aL; aL = bL; bL = t;
    }
    for (int it = 0; it < 4; it++) {
        // G = -0.5*Xt@Xt^T + 1.5I
        { PArg p{tH,tL,tH,tL, -0.5f,0.f,1.5f, 0, 0, mH,mL,Cv, 0,0}; pgemm(smem,m0,n0,p); }
        gridbar();
        if (it < 3) {
            { PArg p{aH,aL,mH,mL, 1.f,0.f,0.f, 0, 0, bH,bL,Cv, tH,tL}; pgemm(smem,m0,n0,p); }
            gridbar();
            bf16* t;
            t = aH; aH = bH; bH = t;
            t = aL; aL = bL; bL = t;
        } else {
            // last X-step writes straight into Pc ([P1||P2] along K: pitch 1024, col offset mat*512)
            PArg p{aH,aL,mH,mL, 1.f,0.f,0.f, 0, 0, PcH + mat*Cv, PcL + mat*Cv, 2*Cv, 0,0};
            pgemm(smem,m0,n0,p);
        }
    }
}

// ---------------- elementwise / reduction kernels ----------------
__global__ void ln_kernel(const float* __restrict__ x, const float* __restrict__ w,
                          bf16* __restrict__ oh, bf16* __restrict__ ol)
{
    const int r = blockIdx.x, tid = threadIdx.x;
    float4 f = ((const float4*)(x + (long)r*Cv))[tid];
    float s = f.x+f.y+f.z+f.w;
    float q = f.x*f.x+f.y*f.y+f.z*f.z+f.w*f.w;
    __shared__ float shs[4], shq[4];
#pragma unroll
    for (int off=16; off>0; off>>=1) {
        s += __shfl_down_sync(0xffffffffu, s, off);
        q += __shfl_down_sync(0xffffffffu, q, off);
    }
    if ((tid&31)==0) { shs[tid>>5]=s; shq[tid>>5]=q; }
    __syncthreads();
    float S = shs[0]+shs[1]+shs[2]+shs[3];
    float Q = shq[0]+shq[1]+shq[2]+shq[3];
    float mean = S*(1.f/Cv);
    float var  = Q*(1.f/Cv) - mean*mean;
    float inv  = rsqrtf(var + 1e-5f);
    float4 wf = ((const float4*)w)[tid];
    float o0=(f.x-mean)*inv*wf.x, o1=(f.y-mean)*inv*wf.y;
    float o2=(f.z-mean)*inv*wf.z, o3=(f.w-mean)*inv*wf.w;
    bf16 h0,h1,h2,h3,l0,l1,l2,l3;
    split2(o0,h0,l0); split2(o1,h1,l1); split2(o2,h2,l2); split2(o3,h3,l3);
    long ofs = (long)r*Cv + tid*4;
    uint2 uh; uh.x=pk2(h0,h1); uh.y=pk2(h2,h3);
    uint2 ul; ul.x=pk2(l0,l1); ul.y=pk2(l2,l3);
    *(uint2*)(oh+ofs)=uh; *(uint2*)(ol+ofs)=ul;
}

// in-place scan combine: q[t] <- rms(z[t]) for t >= d; 4 rows per 512-thr block.
__global__ void pscan_combine(const float* __restrict__ z,
                              bf16* __restrict__ qH, bf16* __restrict__ qL,
                              int d, int mskip)
{
    const int grp = threadIdx.x >> 7;
    const int tid = threadIdx.x & 127;
    const int t = mskip + blockIdx.x * 4 + grp;
    const bool active = (t >= d);
    const int r = blockIdx.y * Tv + t;
    long ofs = (long)r*Cv + tid*4;
    float4 f = *(const float4*)(z+ofs);
    float q = f.x*f.x+f.y*f.y+f.z*f.z+f.w*f.w;
    __shared__ float shq[4][4];
#pragma unroll
    for (int off=16; off>0; off>>=1) q += __shfl_down_sync(0xffffffffu, q, off);
    if ((tid&31)==0) shq[grp][tid>>5]=q;
    __syncthreads();
    float Q = shq[grp][0]+shq[grp][1]+shq[grp][2]+shq[grp][3];
    float sc = rsqrtf(Q*(1.f/Cv) + 1e-6f);
    if (!active) return;
    float o0=f.x*sc, o1=f.y*sc, o2=f.z*sc, o3=f.w*sc;
    bf16 h0,h1,h2,h3,l0,l1,l2,l3;
    split2(o0,h0,l0); split2(o1,h1,l1); split2(o2,h2,l2); split2(o3,h3,l3);
    uint2 uh; uh.x=pk2(h0,h1); uh.y=pk2(h2,h3);
    uint2 ul; ul.x=pk2(l0,l1); ul.y=pk2(l2,l3);
    *(uint2*)(qH+ofs)=uh; *(uint2*)(qL+ofs)=ul;
}

__global__ void mul_split(const bf16* __restrict__ qH, const bf16* __restrict__ qL,
                          const bf16* __restrict__ vH, const bf16* __restrict__ vL,
                          bf16* __restrict__ H, bf16* __restrict__ L)
{
    long i = ((long)blockIdx.x*256 + threadIdx.x)*4;
    uint2 a = *(const uint2*)(qH+i), b = *(const uint2*)(qL+i);
    uint2 c = *(const uint2*)(vH+i), d = *(const uint2*)(vL+i);
    float q0,q1,q2,q3,ql0,ql1,ql2,ql3,v0,v1,v2,v3,vl0,vl1,vl2,vl3;
    up2(a.x,q0,q1); up2(a.y,q2,q3); up2(b.x,ql0,ql1); up2(b.y,ql2,ql3);
    up2(c.x,v0,v1); up2(c.y,v2,v3); up2(d.x,vl0,vl1); up2(d.y,vl2,vl3);
    float o0=(q0+ql0)*(v0+vl0), o1=(q1+ql1)*(v1+vl1);
    float o2=(q2+ql2)*(v2+vl2), o3=(q3+ql3)*(v3+vl3);
    bf16 h0,h1,h2,h3,l0,l1,l2,l3;
    split2(o0,h0,l0); split2(o1,h1,l1); split2(o2,h2,l2); split2(o3,h3,l3);
    uint2 uh; uh.x=pk2(h0,h1); uh.y=pk2(h2,h3);
    uint2 ul; ul.x=pk2(l0,l1); ul.y=pk2(l2,l3);
    *(uint2*)(H+i)=uh; *(uint2*)(L+i)=ul;
}

__global__ void wsplit5(const float* __restrict__ Wq, const float* __restrict__ Wv,
                        const float* __restrict__ Wo, const float* __restrict__ Wfc,
                        const float* __restrict__ Wpr,
                        bf16* WqH, bf16* WqL, bf16* WvH, bf16* WvL,
                        bf16* WoH, bf16* WoL, bf16* WfcH, bf16* WfcL,
                        bf16* WprH, bf16* WprL)
{
    const int S = Cv*Cv;
    long i = (long)blockIdx.x*256 + threadIdx.x;
    const float* W; bf16 *H, *L; long j;
    if      (i < S)       { W=Wq;  H=WqH;  L=WqL;  j=i; }
    else if (i < 2L*S)    { W=Wv;  H=WvH;  L=WvL;  j=i-S; }
    else if (i < 3L*S)    { W=Wo;  H=WoH;  L=WoL;  j=i-2L*S; }
    else if (i < 7L*S)    { W=Wfc; H=WfcH; L=WfcL; j=i-3L*S; }
    else                  { W=Wpr; H=WprH; L=WprL; j=i-7L*S; }
    float x = W[j];
    bf16 h, l; split2(x, h, l);
    H[j] = h; L[j] = l;
}

__global__ void frob1(const float* __restrict__ W1, const float* __restrict__ W2,
                      float* __restrict__ part)
{
    const int row = blockIdx.x, mat = blockIdx.y, tid = threadIdx.x;
    const float* W = mat ? W2 : W1;
    float4 f = ((const float4*)(W + (long)row*Cv))[tid];
    float q = f.x*f.x+f.y*f.y+f.z*f.z+f.w*f.w;
    __shared__ float shq[4];
#pragma unroll
    for (int off=16; off>0; off>>=1) q += __shfl_down_sync(0xffffffffu, q, off);
    if ((tid&31)==0) shq[tid>>5]=q;
    __syncthreads();
    if (tid==0) part[mat*Cv + row] = shq[0]+shq[1]+shq[2]+shq[3];
}

__global__ void frob2(const float* __restrict__ part, float* __restrict__ rn)
{
    const int mat = blockIdx.x, tid = threadIdx.x;
    __shared__ float sh[256];
    sh[tid] = part[mat*Cv + tid] + part[mat*Cv + tid + 256];
    __syncthreads();
    for (int off=128; off>0; off>>=1) {
        if (tid<off) sh[tid] += sh[tid+off];
        __syncthreads();
    }
    if (tid==0) rn[mat] = rsqrtf(sh[0]);
}

__global__ void split_tr_init(const float* __restrict__ W1, const float* __restrict__ W2,
                              const float* __restrict__ rn,
                              bf16* XH, bf16* XL, bf16* XtH, bf16* XtL)
{
    __shared__ float t[32][33];
    const int mat = blockIdx.z;
    const float* W = mat ? W2 : W1;
    const float s = rn[mat];
    const int r0 = blockIdx.y*32, c0 = blockIdx.x*32;
    const int tx = threadIdx.x, ty = threadIdx.y;
    const long mo = (long)mat*Sm;
#pragma unroll
    for (int i = 0; i < 4; i++) {
        int rr = ty + i*8;
        t[rr][tx] = W[(long)(r0+rr)*Cv + c0+tx] * s;
    }
    __syncthreads();
#pragma unroll
    for (int i = 0; i < 4; i++) {
        int rr = ty + i*8;
        bf16 h, l;
        split2(t[rr][tx], h, l);
        XH[mo + (long)(r0+rr)*Cv + c0+tx] = h;
        XL[mo + (long)(r0+rr)*Cv + c0+tx] = l;
        split2(t[tx][rr], h, l);
        XtH[mo + (long)(c0+rr)*Cv + r0+tx] = h;
        XtL[mo + (long)(c0+rr)*Cv + r0+tx] = l;
    }
}

// ---------------- host ----------------
static inline GA mkga(const bf16* Ah, const bf16* Al, const bf16* Bh, const bf16* Bl,
                      int M, int N, int K, int lda, int ldb, long zA = 0, long zB = 0)
{
    GA g; g.Ah=Ah; g.Al=Al; g.Ah2=Ah; g.Al2=Al; g.Bh=Bh; g.Bl=Bl;
    g.M=M; g.N=N; g.K=K; g.K1=K; g.lda=lda; g.ldb=ldb; g.mskip=0; g.zA=zA; g.zB=zB;
    return g;
}
static inline TEpi te()
{
    TEpi e; e.alpha=1.f; e.beta=1.f; e.diag=0.f; e.add=0; e.zAdd=0;
    e.gelu=0; e.outF=0; e.outH=0; e.outL=0; e.zOut=0; e.outTH=0; e.outTL=0;
    return e;
}

#define SM128 (3*4*128*64)                   // 98304: 128x128 tiles, 3 stages

extern "C" void kernel_launch(void* const* d_in, const int* in_sizes, int n_in,
                              void* d_out, int out_size)
{
    const float* x   = (const float*)d_in[0];
    const float* ln1 = (const float*)d_in[1];
    const float* Wq  = (const float*)d_in[2];
    const float* Wv  = (const float*)d_in[3];
    const float* Wo  = (const float*)d_in[4];
    // d_in[5] = identity : mathematically unused (rows computed from it are discarded)
    const float* Wp1 = (const float*)d_in[6];
    const float* Wp2 = (const float*)d_in[7];
    const float* ln2 = (const float*)d_in[8];
    const float* Wfc = (const float*)d_in[9];
    const float* Wpr = (const float*)d_in[10];
    float* out = (float*)d_out;

    cudaFuncSetAttribute(mma_gemm<128,128,2,2,3>, cudaFuncAttributeMaxDynamicSharedMemorySize, SM128);

    static cudaStream_t sP = 0, sM = 0;
    static cudaEvent_t evF = 0, evJ = 0, evM = 0;
    if (!sP) {
        cudaStreamCreateWithFlags(&sP, cudaStreamNonBlocking);
        cudaStreamCreateWithFlags(&sM, cudaStreamNonBlocking);
        cudaEventCreateWithFlags(&evF, cudaEventDisableTiming);
        cudaEventCreateWithFlags(&evJ, cudaEventDisableTiming);
        cudaEventCreateWithFlags(&evM, cudaEventDisableTiming);
    }

    bf16 *qH,*qL,*vH,*vL,*hH,*hL,*fcH,*fcL;
    bf16 *WqH,*WqL,*WvH,*WvL,*WoH,*WoL,*WfcH,*WfcL,*WprH,*WprL;
    bf16 *XaH,*XaL,*XbH,*XbL,*XtH,*XtL,*YH,*YL,*MH,*ML,*PcH,*PcL;
    float *z,*YF,*part,*rn;
    cudaGetSymbolAddress((void**)&qH, g_qH);   cudaGetSymbolAddress((void**)&qL, g_qL);
    cudaGetSymbolAddress((void**)&vH, g_vH);   cudaGetSymbolAddress((void**)&vL, g_vL);
    cudaGetSymbolAddress((void**)&z,  g_z);
    cudaGetSymbolAddress((void**)&hH, g_hH);   cudaGetSymbolAddress((void**)&hL, g_hL);
    cudaGetSymbolAddress((void**)&fcH, g_fcH); cudaGetSymbolAddress((void**)&fcL, g_fcL);
    cudaGetSymbolAddress((void**)&WqH, g_WqH); cudaGetSymbolAddress((void**)&WqL, g_WqL);
    cudaGetSymbolAddress((void**)&WvH, g_WvH); cudaGetSymbolAddress((void**)&WvL, g_WvL);
    cudaGetSymbolAddress((void**)&WoH, g_WoH); cudaGetSymbolAddress((void**)&WoL, g_WoL);
    cudaGetSymbolAddress((void**)&WfcH,g_WfcH); cudaGetSymbolAddress((void**)&WfcL,g_WfcL);
    cudaGetSymbolAddress((void**)&WprH,g_WprH); cudaGetSymbolAddress((void**)&WprL,g_WprL);
    cudaGetSymbolAddress((void**)&XaH, g_XaH); cudaGetSymbolAddress((void**)&XaL, g_XaL);
    cudaGetSymbolAddress((void**)&XbH, g_XbH); cudaGetSymbolAddress((void**)&XbL, g_XbL);
    cudaGetSymbolAddress((void**)&XtH, g_XtH); cudaGetSymbolAddress((void**)&XtL, g_XtL);
    cudaGetSymbolAddress((void**)&YH,  g_YH);  cudaGetSymbolAddress((void**)&YL,  g_YL);
    cudaGetSymbolAddress((void**)&MH,  g_MH);  cudaGetSymbolAddress((void**)&ML,  g_ML);
    cudaGetSymbolAddress((void**)&PcH, g_PcH); cudaGetSymbolAddress((void**)&PcL, g_PcL);
    cudaGetSymbolAddress((void**)&YF,  g_YF);
    cudaGetSymbolAddress((void**)&part,g_part);
    cudaGetSymbolAddress((void**)&rn,  g_rn);

    // ---- fork ----
    cudaEventRecord(evF, 0);
    cudaStreamWaitEvent(sP, evF, 0);
    cudaStreamWaitEvent(sM, evF, 0);

    {   // polar chain (stream sP): 3 small launches + ONE persistent fused kernel
        frob1<<<dim3(Cv,2),128,0,sP>>>(Wp1, Wp2, part);
        frob2<<<2,256,0,sP>>>(part, rn);
        split_tr_init<<<dim3(16,16,2),dim3(32,8),0,sP>>>(Wp1, Wp2, rn, XaH, XaL, XtH, XtL);
        polar_chain<<<256,256,0,sP>>>(XaH, XaL, XbH, XbL, XtH, XtL,
                                      YH, YL, MH, ML, YF, PcH, PcL);
        cudaEventRecord(evJ, sP);
    }

    {   // main prep: weight splits + ln + q/v GEMMs (stream sM, concurrent w/ polar)
        wsplit5<<<(11*Cv*Cv)/256,256,0,sM>>>(Wq, Wv, Wo, Wfc, Wpr,
            WqH, WqL, WvH, WvL, WoH, WoL, WfcH, WfcL, WprH, WprL);
        ln_kernel<<<Rv,128,0,sM>>>(x, ln1, hH, hL);
        GA gq = mkga(hH, hL, WqH, WqL, Rv, Cv, Cv, Cv, Cv);
        TEpi eq = te(); eq.outH = qH + GUARDE; eq.outL = qL + GUARDE;
        mma_gemm<128,128,2,2,3><<<dim3(Cv/128, Rv/128), 256, SM128, sM>>>(gq, eq);
        GA gv = mkga(hH, hL, WvH, WvL, Rv, Cv, Cv, Cv, Cv);
        TEpi ev = te(); ev.outH = vH; ev.outL = vL;
        mma_gemm<128,128,2,2,3><<<dim3(Cv/128, Rv/128), 256, SM128, sM>>>(gv, ev);
        cudaEventRecord(evM, sM);
    }

    // ---- join: scan needs Pc (sP) and q (sM) ----
    cudaStreamWaitEvent(0, evJ, 0);
    cudaStreamWaitEvent(0, evM, 0);

    for (int d = 1; d < Tv; d <<= 1) {
        const int mskip = d & ~127;
        // z = qshift @ P1^T + q @ P2^T : single GEMM, K=1024
        GA gs = mkga(qH + GUARDE, qL + GUARDE, PcH, PcL, Rv, Cv, 2*Cv, Cv, 2*Cv);
        gs.Ah = qH + GUARDE - (long)d*Cv;
        gs.Al = qL + GUARDE - (long)d*Cv;
        gs.K1 = Cv;
        gs.mskip = mskip;
        gs.zA = (long)Tv*Cv;
        TEpi es = te(); es.outF = z; es.zOut = (long)Tv*Cv;
        mma_gemm<128,128,2,2,3><<<dim3(Cv/128, (Tv-mskip)/128, Bv), 256, SM128>>>(gs, es);
        pscan_combine<<<dim3((Tv-mskip)/4, Bv),512>>>(z, qH + GUARDE, qL + GUARDE, d, mskip);
    }

    // x1 = x + (q*v) @ Wo^T   (into d_out)
    mul_split<<<(Rv*Cv/4)/256,256>>>(qH + GUARDE, qL + GUARDE, vH, vL, hH, hL);
    {
        GA go = mkga(hH, hL, WoH, WoL, Rv, Cv, Cv, Cv, Cv);
        TEpi er = te(); er.add = x; er.outF = out;
        mma_gemm<128,128,2,2,3><<<dim3(Cv/128, Rv/128), 256, SM128>>>(go, er);
    }

    // ---- MLP branch ----
    ln_kernel<<<Rv,128>>>(out, ln2, hH, hL);
    {
        GA gf = mkga(hH, hL, WfcH, WfcL, Rv, Fv, Cv, Cv, Cv);
        TEpi eg = te(); eg.gelu = 1; eg.outH = fcH; eg.outL = fcL;
        mma_gemm<128,128,2,2,3><<<dim3(Fv/128, Rv/128), 256, SM128>>>(gf, eg);
        GA gr = mkga(fcH, fcL, WprH, WprL, Rv, Cv, Fv, Fv, Fv);
        TEpi er2 = te(); er2.add = out; er2.outF = out;
        mma_gemm<128,128,2,2,3><<<dim3(Cv/128, Rv/128), 256, SM128>>>(gr, er2);
    }
}